// round 1
// baseline (speedup 1.0000x reference)
#include <cuda_runtime.h>
#include <math.h>

// Problem constants
#define BB   4
#define LL   1024
#define DD   768
#define HH   12
#define FF_  3072
#define DK_  64
#define PP   32
#define MAXD_ 256
#define ML   (BB*LL)   // 4096 rows

// ---------------- scratch (device globals; no runtime allocation) ----------
__device__ float g_qin[ML*DD];
__device__ float g_Q[ML*DD];
__device__ float g_K[ML*DD];
__device__ float g_V[ML*DD];
__device__ float g_ctx[ML*DD];
__device__ float g_res1[ML*DD];
__device__ float g_h2[ML*DD];
__device__ float g_ff[ML*FF_];

// ---------------- LayerNorm ----------------
__global__ void ln_kernel(const float* __restrict__ x, const float* __restrict__ g,
                          const float* __restrict__ b, float* __restrict__ y, float eps) {
    int row = blockIdx.x;
    const float* xr = x + (size_t)row * DD;
    __shared__ float red[256];
    int tid = threadIdx.x;

    float s = 0.f;
    for (int d = tid; d < DD; d += 256) s += xr[d];
    red[tid] = s; __syncthreads();
    #pragma unroll
    for (int o = 128; o > 0; o >>= 1) { if (tid < o) red[tid] += red[tid + o]; __syncthreads(); }
    float mu = red[0] * (1.f / DD);
    __syncthreads();

    float v = 0.f;
    for (int d = tid; d < DD; d += 256) { float t = xr[d] - mu; v += t * t; }
    red[tid] = v; __syncthreads();
    #pragma unroll
    for (int o = 128; o > 0; o >>= 1) { if (tid < o) red[tid] += red[tid + o]; __syncthreads(); }
    float inv = rsqrtf(red[0] * (1.f / DD) + eps);

    float* yr = y + (size_t)row * DD;
    for (int d = tid; d < DD; d += 256)
        yr[d] = (xr[d] - mu) * inv * g[d] + b[d];
}

// ---------------- 128x128x8 SGEMM, 256 threads, 8x8 microtile ----------------
// EPI: 0 = bias; 1 = bias + residual; 2 = bias + exact GELU
template<int EPI>
__global__ void gemm128(const float* __restrict__ A, const float* __restrict__ W,
                        const float* __restrict__ bias, const float* __restrict__ res,
                        float* __restrict__ C, int K, int N) {
    __shared__ float Ast[8][132];   // transposed A tile: Ast[k][r]
    __shared__ float Ws[8][128];    // W tile: Ws[k][c]

    int tid = threadIdx.x;
    int tx = tid & 15, ty = tid >> 4;
    int row0 = blockIdx.y * 128, col0 = blockIdx.x * 128;

    float acc[8][8];
    #pragma unroll
    for (int i = 0; i < 8; i++)
        #pragma unroll
        for (int j = 0; j < 8; j++) acc[i][j] = 0.f;

    int ar = tid >> 1, ac = (tid & 1) * 4;
    int wr = tid >> 5, wc = (tid & 31) * 4;

    for (int kk = 0; kk < K; kk += 8) {
        float4 av = *(const float4*)(A + (size_t)(row0 + ar) * K + kk + ac);
        float4 wv = *(const float4*)(W + (size_t)(kk + wr) * N + col0 + wc);
        Ast[ac + 0][ar] = av.x;
        Ast[ac + 1][ar] = av.y;
        Ast[ac + 2][ar] = av.z;
        Ast[ac + 3][ar] = av.w;
        *(float4*)&Ws[wr][wc] = wv;
        __syncthreads();
        #pragma unroll
        for (int k = 0; k < 8; k++) {
            float4 a0 = *(const float4*)&Ast[k][ty * 8];
            float4 a1 = *(const float4*)&Ast[k][ty * 8 + 4];
            float4 w0 = *(const float4*)&Ws[k][tx * 8];
            float4 w1 = *(const float4*)&Ws[k][tx * 8 + 4];
            float a[8] = {a0.x, a0.y, a0.z, a0.w, a1.x, a1.y, a1.z, a1.w};
            float w[8] = {w0.x, w0.y, w0.z, w0.w, w1.x, w1.y, w1.z, w1.w};
            #pragma unroll
            for (int i = 0; i < 8; i++)
                #pragma unroll
                for (int j = 0; j < 8; j++) acc[i][j] += a[i] * w[j];
        }
        __syncthreads();
    }

    // epilogue
    #pragma unroll
    for (int i = 0; i < 8; i++) {
        int rr = row0 + ty * 8 + i;
        #pragma unroll
        for (int jb = 0; jb < 8; jb += 4) {
            int cc = col0 + tx * 8 + jb;
            float4 o;
            float v0 = acc[i][jb + 0] + bias[cc + 0];
            float v1 = acc[i][jb + 1] + bias[cc + 1];
            float v2 = acc[i][jb + 2] + bias[cc + 2];
            float v3 = acc[i][jb + 3] + bias[cc + 3];
            if (EPI == 1) {
                const float* rp = res + (size_t)rr * N + cc;
                v0 += rp[0]; v1 += rp[1]; v2 += rp[2]; v3 += rp[3];
            }
            if (EPI == 2) {
                v0 = 0.5f * v0 * (1.f + erff(v0 * 0.70710678118654752f));
                v1 = 0.5f * v1 * (1.f + erff(v1 * 0.70710678118654752f));
                v2 = 0.5f * v2 * (1.f + erff(v2 * 0.70710678118654752f));
                v3 = 0.5f * v3 * (1.f + erff(v3 * 0.70710678118654752f));
            }
            o.x = v0; o.y = v1; o.z = v2; o.w = v3;
            *(float4*)(C + (size_t)rr * N + cc) = o;
        }
    }
}

// ---------------- fused attention (flash-style, 64-query tiles) ----------------
// dyn smem: Qst[64][64] (d-major), Kst[64][64] (d-major), Vs[64][64], St[64][68]
#define ATTN_SMEM ((4096 * 3 + 64 * 68) * 4)

__global__ void attn_kernel(const float* __restrict__ Q, const float* __restrict__ Km,
                            const float* __restrict__ Vm, const float* __restrict__ rel_emb,
                            const float* __restrict__ ptab, const int* __restrict__ pids,
                            const float* __restrict__ lex, float* __restrict__ ctx) {
    extern __shared__ float dsm[];
    float* Qst = dsm;           // [d][r]
    float* Kst = dsm + 4096;    // [d][j]
    float* Vs  = dsm + 8192;    // [j][c]
    float* St  = dsm + 12288;   // [j][r], stride 68

    __shared__ int pidq[64], pidk[64];
    __shared__ float lexs[64], mrow[64], lrow[64], arow[64];

    int tid = threadIdx.x;
    int h = blockIdx.y, bb = blockIdx.z;
    int i0 = blockIdx.x * 64;
    int tx = tid & 15, ty = tid >> 4;
    int lr = tid >> 2, lq = tid & 3;

    // load Q tile transposed, pre-scaled by 1/sqrt(dk)
    {
        int r = tid >> 2, seg = tid & 3;
        const float* src = Q + (size_t)(bb * LL + i0 + r) * DD + h * 64 + seg * 16;
        #pragma unroll
        for (int u = 0; u < 4; u++) {
            float4 v = *(const float4*)(src + u * 4);
            int d = seg * 16 + u * 4;
            Qst[(d + 0) * 64 + r] = v.x * 0.125f;
            Qst[(d + 1) * 64 + r] = v.y * 0.125f;
            Qst[(d + 2) * 64 + r] = v.z * 0.125f;
            Qst[(d + 3) * 64 + r] = v.w * 0.125f;
        }
    }
    if (tid < 64) {
        pidq[tid] = pids[bb * LL + i0 + tid];
        mrow[tid] = -1e30f;
        lrow[tid] = 0.f;
    }

    float O[4][4];
    #pragma unroll
    for (int i = 0; i < 4; i++)
        #pragma unroll
        for (int j = 0; j < 4; j++) O[i][j] = 0.f;

    for (int t = 0; t < 16; t++) {
        int j0 = t * 64;
        // load K (transposed) and V tiles
        {
            int r = tid >> 2, seg = tid & 3;
            const float* ks = Km + (size_t)(bb * LL + j0 + r) * DD + h * 64 + seg * 16;
            const float* vs = Vm + (size_t)(bb * LL + j0 + r) * DD + h * 64 + seg * 16;
            #pragma unroll
            for (int u = 0; u < 4; u++) {
                float4 kv = *(const float4*)(ks + u * 4);
                int d = seg * 16 + u * 4;
                Kst[(d + 0) * 64 + r] = kv.x;
                Kst[(d + 1) * 64 + r] = kv.y;
                Kst[(d + 2) * 64 + r] = kv.z;
                Kst[(d + 3) * 64 + r] = kv.w;
                float4 vv = *(const float4*)(vs + u * 4);
                *(float4*)&Vs[r * 64 + seg * 16 + u * 4] = vv;
            }
        }
        if (tid < 64) {
            pidk[tid] = pids[bb * LL + j0 + tid];
            lexs[tid] = lex[bb * LL + j0 + tid];
        }
        __syncthreads();

        // S[j][r] = K[j] . Qscaled[r]   (thread owns j = ty*4+i, r = tx*4+jj)
        float s[4][4];
        #pragma unroll
        for (int i = 0; i < 4; i++)
            #pragma unroll
            for (int j = 0; j < 4; j++) s[i][j] = 0.f;
        #pragma unroll 8
        for (int d = 0; d < 64; d++) {
            float4 a = *(const float4*)&Kst[d * 64 + ty * 4];
            float4 w = *(const float4*)&Qst[d * 64 + tx * 4];
            float av[4] = {a.x, a.y, a.z, a.w};
            float wv[4] = {w.x, w.y, w.z, w.w};
            #pragma unroll
            for (int i = 0; i < 4; i++)
                #pragma unroll
                for (int j = 0; j < 4; j++) s[i][j] += av[i] * wv[j];
        }
        // add biases, write to St
        #pragma unroll
        for (int i = 0; i < 4; i++) {
            int jl = ty * 4 + i;
            int jg = j0 + jl;
            int pk = pidk[jl];
            float lx = lexs[jl];
            #pragma unroll
            for (int jj = 0; jj < 4; jj++) {
                int rl = tx * 4 + jj;
                int rg = i0 + rl;
                int rel = jg - rg;
                rel = min(max(rel, -MAXD_), MAXD_);
                float pb = rel_emb[(rel + MAXD_) * HH + h];
                float pt = ptab[(pidq[rl] * PP + pk) * HH + h];
                St[jl * 68 + rl] = s[i][jj] + pb + pt + lx;
            }
        }
        __syncthreads();

        // online softmax: 4 threads per query row
        {
            float mo = mrow[lr];
            float mx = -1e30f;
            #pragma unroll
            for (int k = 0; k < 16; k++)
                mx = fmaxf(mx, St[(lq * 16 + k) * 68 + lr]);
            mx = fmaxf(mx, __shfl_xor_sync(0xffffffffu, mx, 1));
            mx = fmaxf(mx, __shfl_xor_sync(0xffffffffu, mx, 2));
            float mn = fmaxf(mo, mx);
            float a = __expf(mo - mn);
            float sum = 0.f;
            #pragma unroll
            for (int k = 0; k < 16; k++) {
                int idx = (lq * 16 + k) * 68 + lr;
                float e = __expf(St[idx] - mn);
                St[idx] = e;
                sum += e;
            }
            sum += __shfl_xor_sync(0xffffffffu, sum, 1);
            sum += __shfl_xor_sync(0xffffffffu, sum, 2);
            if (lq == 0) {
                mrow[lr] = mn;
                lrow[lr] = lrow[lr] * a + sum;
                arow[lr] = a;
            }
        }
        __syncthreads();

        // rescale + O += P @ V  (thread owns rows ty*4+i, cols tx*4+jj)
        #pragma unroll
        for (int i = 0; i < 4; i++) {
            float al = arow[ty * 4 + i];
            #pragma unroll
            for (int j = 0; j < 4; j++) O[i][j] *= al;
        }
        #pragma unroll 8
        for (int j = 0; j < 64; j++) {
            float4 p = *(const float4*)&St[j * 68 + ty * 4];
            float4 v = *(const float4*)&Vs[j * 64 + tx * 4];
            float pv[4] = {p.x, p.y, p.z, p.w};
            float vv[4] = {v.x, v.y, v.z, v.w};
            #pragma unroll
            for (int i = 0; i < 4; i++)
                #pragma unroll
                for (int jj = 0; jj < 4; jj++) O[i][jj] += pv[i] * vv[jj];
        }
        __syncthreads();
    }

    // finalize: divide by l, store
    #pragma unroll
    for (int i = 0; i < 4; i++) {
        int rl = ty * 4 + i;
        float inv = 1.f / lrow[rl];
        float4 o;
        o.x = O[i][0] * inv; o.y = O[i][1] * inv;
        o.z = O[i][2] * inv; o.w = O[i][3] * inv;
        *(float4*)(ctx + (size_t)(bb * LL + i0 + rl) * DD + h * 64 + tx * 4) = o;
    }
}

// ---------------- launch ----------------
extern "C" void kernel_launch(void* const* d_in, const int* in_sizes, int n_in,
                              void* d_out, int out_size) {
    const float* x      = (const float*)d_in[0];
    const int*   postag = (const int*)  d_in[1];
    const float* lexm   = (const float*)d_in[2];
    const float* ln1g   = (const float*)d_in[3];
    const float* ln1b   = (const float*)d_in[4];
    const float* Wq     = (const float*)d_in[5];
    const float* bq     = (const float*)d_in[6];
    const float* Wk     = (const float*)d_in[7];
    const float* bk     = (const float*)d_in[8];
    const float* Wv     = (const float*)d_in[9];
    const float* bv     = (const float*)d_in[10];
    const float* Wo     = (const float*)d_in[11];
    const float* bo     = (const float*)d_in[12];
    const float* rel    = (const float*)d_in[13];
    const float* ptab   = (const float*)d_in[14];
    const float* ln2g   = (const float*)d_in[15];
    const float* ln2b   = (const float*)d_in[16];
    const float* W1     = (const float*)d_in[17];
    const float* b1     = (const float*)d_in[18];
    const float* W2     = (const float*)d_in[19];
    const float* b2     = (const float*)d_in[20];
    float* out = (float*)d_out;

    float *qin, *Qb, *Kb, *Vb, *ctx, *res1, *h2, *ff;
    cudaGetSymbolAddress((void**)&qin,  g_qin);
    cudaGetSymbolAddress((void**)&Qb,   g_Q);
    cudaGetSymbolAddress((void**)&Kb,   g_K);
    cudaGetSymbolAddress((void**)&Vb,   g_V);
    cudaGetSymbolAddress((void**)&ctx,  g_ctx);
    cudaGetSymbolAddress((void**)&res1, g_res1);
    cudaGetSymbolAddress((void**)&h2,   g_h2);
    cudaGetSymbolAddress((void**)&ff,   g_ff);

    cudaFuncSetAttribute(attn_kernel, cudaFuncAttributeMaxDynamicSharedMemorySize, ATTN_SMEM);

    // 1. LN1
    ln_kernel<<<ML, 256>>>(x, ln1g, ln1b, qin, 1e-6f);
    // 2. QKV projections
    gemm128<0><<<dim3(DD / 128, ML / 128), 256>>>(qin, Wq, bq, nullptr, Qb, DD, DD);
    gemm128<0><<<dim3(DD / 128, ML / 128), 256>>>(qin, Wk, bk, nullptr, Kb, DD, DD);
    gemm128<0><<<dim3(DD / 128, ML / 128), 256>>>(qin, Wv, bv, nullptr, Vb, DD, DD);
    // 3. attention (fused bias + softmax + PV)
    attn_kernel<<<dim3(LL / 64, HH, BB), 256, ATTN_SMEM>>>(Qb, Kb, Vb, rel, ptab, postag, lexm, ctx);
    // 4. output projection + residual
    gemm128<1><<<dim3(DD / 128, ML / 128), 256>>>(ctx, Wo, bo, x, res1, DD, DD);
    // 5. LN2
    ln_kernel<<<ML, 256>>>(res1, ln2g, ln2b, h2, 1e-5f);
    // 6. FFN up + GELU
    gemm128<2><<<dim3(FF_ / 128, ML / 128), 256>>>(h2, W1, b1, nullptr, ff, DD, FF_);
    // 7. FFN down + bias + residual -> out
    gemm128<1><<<dim3(DD / 128, ML / 128), 256>>>(ff, W2, b2, res1, out, FF_, DD);
}

// round 4
// speedup vs baseline: 1.4513x; 1.4513x over previous
#include <cuda_runtime.h>
#include <math.h>
#include <stdint.h>

// Problem constants
#define BB   4
#define LL   1024
#define DD   768
#define HH   12
#define FF_  3072
#define PP   32
#define MAXD_ 256
#define ML   (BB*LL)   // 4096 rows

// ---------------- scratch (device globals; no runtime allocation) ----------
__device__ float g_qin[ML*DD];
__device__ float g_Q[ML*DD];
__device__ float g_K[ML*DD];
__device__ float g_V[ML*DD];
__device__ float g_ctx[ML*DD];
__device__ float g_res1[ML*DD];
__device__ float g_h2[ML*DD];
__device__ float g_ff[ML*FF_];
// transposed weights [N,K] (tf32-rounded)
__device__ float g_WqT[DD*DD];
__device__ float g_WkT[DD*DD];
__device__ float g_WvT[DD*DD];
__device__ float g_WoT[DD*DD];
__device__ float g_W1T[FF_*DD];
__device__ float g_W2T[DD*FF_];

// single extern shared symbol for all kernels
extern __shared__ char smem_raw[];

// ======================= helpers =====================
__device__ __forceinline__ uint32_t smem_u32(const void* p) {
    uint32_t a;
    asm("{ .reg .u64 t; cvta.to.shared.u64 t, %1; cvt.u32.u64 %0, t; }" : "=r"(a) : "l"(p));
    return a;
}
__device__ __forceinline__ uint32_t f2tf32(float f) {
    uint32_t o; asm("cvt.rna.tf32.f32 %0, %1;" : "=r"(o) : "f"(f)); return o;
}
__device__ __forceinline__ float tf32r(float f) {   // round value to tf32 grid
    return __uint_as_float(f2tf32(f));
}

#define CP_ASYNC16(dst, src) \
    asm volatile("cp.async.ca.shared.global [%0], [%1], 16;" :: "r"(dst), "l"(src) : "memory")
#define CP_COMMIT()  asm volatile("cp.async.commit_group;" ::: "memory")
#define CP_WAIT1()   asm volatile("cp.async.wait_group 1;" ::: "memory")

__device__ __forceinline__ void mma_tf32(float c[4], uint32_t a0, uint32_t a1,
                                         uint32_t a2, uint32_t a3,
                                         uint32_t b0, uint32_t b1) {
    asm volatile(
        "mma.sync.aligned.m16n8k8.row.col.f32.tf32.tf32.f32 "
        "{%0,%1,%2,%3}, {%4,%5,%6,%7}, {%8,%9}, {%0,%1,%2,%3};"
        : "+f"(c[0]), "+f"(c[1]), "+f"(c[2]), "+f"(c[3])
        : "r"(a0), "r"(a1), "r"(a2), "r"(a3), "r"(b0), "r"(b1));
}

// ---------------- weight transpose (+tf32 round): dst[N,K] = src[K,N] -----
__global__ void transpose_k(const float* __restrict__ src, float* __restrict__ dst,
                            int R, int C) {  // src R x C
    __shared__ float t[32][33];
    int c0 = blockIdx.x * 32, r0 = blockIdx.y * 32;
    int x = threadIdx.x, y = threadIdx.y;
    #pragma unroll
    for (int i = 0; i < 32; i += 8)
        t[y + i][x] = src[(size_t)(r0 + y + i) * C + c0 + x];
    __syncthreads();
    #pragma unroll
    for (int i = 0; i < 32; i += 8)
        dst[(size_t)(c0 + y + i) * R + r0 + x] = tf32r(t[x][y + i]);
}

// ---------------- LayerNorm (tf32-rounded output) ----------------
__global__ void ln_kernel(const float* __restrict__ x, const float* __restrict__ g,
                          const float* __restrict__ b, float* __restrict__ y, float eps) {
    int row = blockIdx.x;
    const float* xr = x + (size_t)row * DD;
    __shared__ float red[256];
    int tid = threadIdx.x;

    float s = 0.f;
    for (int d = tid; d < DD; d += 256) s += xr[d];
    red[tid] = s; __syncthreads();
    #pragma unroll
    for (int o = 128; o > 0; o >>= 1) { if (tid < o) red[tid] += red[tid + o]; __syncthreads(); }
    float mu = red[0] * (1.f / DD);
    __syncthreads();

    float v = 0.f;
    for (int d = tid; d < DD; d += 256) { float t = xr[d] - mu; v += t * t; }
    red[tid] = v; __syncthreads();
    #pragma unroll
    for (int o = 128; o > 0; o >>= 1) { if (tid < o) red[tid] += red[tid + o]; __syncthreads(); }
    float inv = rsqrtf(red[0] * (1.f / DD) + eps);

    float* yr = y + (size_t)row * DD;
    for (int d = tid; d < DD; d += 256)
        yr[d] = tf32r((xr[d] - mu) * inv * g[d] + b[d]);
}

// ============ mma.sync tf32 GEMM: C[M,N] = A[M,K] @ Bt[N,K]^T + epi ========
// 128x128 tile per CTA, 8 warps (warp tile 32x64), 3-stage cp.async, KC=32.
// SMEM per stage per operand: [q (8)][m (128)][4] floats = 4096 words.
// EPI: 0 = bias; 1 = bias + residual; 2 = bias + exact GELU
#define NSTAGE 3
#define GSMEM (NSTAGE * 2 * 4096 * 4)   // 98304 bytes

template<int EPI, int TF32OUT>
__global__ __launch_bounds__(256) void mma_gemm(
    const float* __restrict__ A, const float* __restrict__ Bt,
    const float* __restrict__ bias, const float* __restrict__ res,
    float* __restrict__ C, int K, int N) {
    float* sm = (float*)smem_raw;
    uint32_t smem_base = smem_u32(sm);

    int tid = threadIdx.x;
    int wid = tid >> 5, lane = tid & 31;
    int r = lane >> 2, l = lane & 3;
    int row0 = blockIdx.y * 128, col0 = blockIdx.x * 128;
    int m0 = (wid & 3) * 32, n0 = (wid >> 2) * 64;

    // cp.async source/dest mapping: quad = u*256 + tid -> q = tid&7, m = u*32 + (tid>>3)
    int qq = tid & 7;
    int mm = tid >> 3;
    const float* srcA = A + (size_t)(row0 + mm) * K + qq * 4;
    const float* srcB = Bt + (size_t)(col0 + mm) * K + qq * 4;
    uint32_t dA0 = smem_base + (qq * 512 + mm * 4) * 4;
    uint32_t dB0 = dA0 + 16384;

    int nc = K >> 5;   // chunks of 32

    float acc[2][8][4];
    #pragma unroll
    for (int i = 0; i < 2; i++)
        #pragma unroll
        for (int j = 0; j < 8; j++)
            #pragma unroll
            for (int k = 0; k < 4; k++) acc[i][j][k] = 0.f;

    // prologue: issue stages 0..NSTAGE-2
    #pragma unroll
    for (int s = 0; s < NSTAGE - 1; s++) {
        uint32_t so = s * 32768;
        #pragma unroll
        for (int u = 0; u < 4; u++) {
            CP_ASYNC16(dA0 + so + u * 512, srcA + (size_t)(s * 32) + (size_t)u * 32 * K);
            CP_ASYNC16(dB0 + so + u * 512, srcB + (size_t)(s * 32) + (size_t)u * 32 * K);
        }
        CP_COMMIT();
    }

    for (int c = 0; c < nc; c++) {
        CP_WAIT1();
        __syncthreads();
        int nstg = c + NSTAGE - 1;
        if (nstg < nc) {
            uint32_t so = (nstg % NSTAGE) * 32768;
            #pragma unroll
            for (int u = 0; u < 4; u++) {
                CP_ASYNC16(dA0 + so + u * 512, srcA + (size_t)(nstg * 32) + (size_t)u * 32 * K);
                CP_ASYNC16(dB0 + so + u * 512, srcB + (size_t)(nstg * 32) + (size_t)u * 32 * K);
            }
        }
        CP_COMMIT();

        const float* sA = sm + (c % NSTAGE) * 8192;
        const float* sB = sA + 4096;
        #pragma unroll
        for (int ks = 0; ks < 4; ks++) {
            int kb = ks * 1024;
            uint32_t a[2][4];
            #pragma unroll
            for (int mi = 0; mi < 2; mi++) {
                int ao = kb + (m0 + 16 * mi + r) * 4 + l;
                a[mi][0] = __float_as_uint(sA[ao]);
                a[mi][1] = __float_as_uint(sA[ao + 32]);
                a[mi][2] = __float_as_uint(sA[ao + 512]);
                a[mi][3] = __float_as_uint(sA[ao + 544]);
            }
            #pragma unroll
            for (int nj = 0; nj < 8; nj++) {
                int bo = kb + (n0 + 8 * nj + r) * 4 + l;
                uint32_t b0 = __float_as_uint(sB[bo]);
                uint32_t b1 = __float_as_uint(sB[bo + 512]);
                mma_tf32(acc[0][nj], a[0][0], a[0][1], a[0][2], a[0][3], b0, b1);
                mma_tf32(acc[1][nj], a[1][0], a[1][1], a[1][2], a[1][3], b0, b1);
            }
        }
    }

    // epilogue
    #pragma unroll
    for (int mi = 0; mi < 2; mi++) {
        int rr = row0 + m0 + 16 * mi + r;
        #pragma unroll
        for (int nj = 0; nj < 8; nj++) {
            int cc = col0 + n0 + 8 * nj + 2 * l;
            float b0 = bias[cc], b1 = bias[cc + 1];
            float v0 = acc[mi][nj][0] + b0;
            float v1 = acc[mi][nj][1] + b1;
            float v2 = acc[mi][nj][2] + b0;
            float v3 = acc[mi][nj][3] + b1;
            if (EPI == 1) {
                const float* rp0 = res + (size_t)rr * N + cc;
                const float* rp1 = res + (size_t)(rr + 8) * N + cc;
                v0 += rp0[0]; v1 += rp0[1];
                v2 += rp1[0]; v3 += rp1[1];
            }
            if (EPI == 2) {
                v0 = 0.5f * v0 * (1.f + erff(v0 * 0.70710678118654752f));
                v1 = 0.5f * v1 * (1.f + erff(v1 * 0.70710678118654752f));
                v2 = 0.5f * v2 * (1.f + erff(v2 * 0.70710678118654752f));
                v3 = 0.5f * v3 * (1.f + erff(v3 * 0.70710678118654752f));
            }
            if (TF32OUT) {
                v0 = tf32r(v0); v1 = tf32r(v1); v2 = tf32r(v2); v3 = tf32r(v3);
            }
            float2 o01 = { v0, v1 };
            float2 o23 = { v2, v3 };
            *(float2*)(C + (size_t)rr * N + cc) = o01;
            *(float2*)(C + (size_t)(rr + 8) * N + cc) = o23;
        }
    }
}

// ---------------- fused attention (flash-style, 64-query tiles) ----------------
#define ATTN_SMEM ((4096 * 3 + 64 * 68) * 4)

__global__ void attn_kernel(const float* __restrict__ Q, const float* __restrict__ Km,
                            const float* __restrict__ Vm, const float* __restrict__ rel_emb,
                            const float* __restrict__ ptab, const int* __restrict__ pids,
                            const float* __restrict__ lex, float* __restrict__ ctx) {
    float* dsm = (float*)smem_raw;
    float* Qst = dsm;           // [d][r]
    float* Kst = dsm + 4096;    // [d][j]
    float* Vs  = dsm + 8192;    // [j][c]
    float* St  = dsm + 12288;   // [j][r], stride 68

    __shared__ int pidq[64], pidk[64];
    __shared__ float lexs[64], mrow[64], lrow[64], arow[64];

    int tid = threadIdx.x;
    int h = blockIdx.y, bb = blockIdx.z;
    int i0 = blockIdx.x * 64;
    int tx = tid & 15, ty = tid >> 4;
    int lr = tid >> 2, lq = tid & 3;

    {
        int r = tid >> 2, seg = tid & 3;
        const float* src = Q + (size_t)(bb * LL + i0 + r) * DD + h * 64 + seg * 16;
        #pragma unroll
        for (int u = 0; u < 4; u++) {
            float4 v = *(const float4*)(src + u * 4);
            int d = seg * 16 + u * 4;
            Qst[(d + 0) * 64 + r] = v.x * 0.125f;
            Qst[(d + 1) * 64 + r] = v.y * 0.125f;
            Qst[(d + 2) * 64 + r] = v.z * 0.125f;
            Qst[(d + 3) * 64 + r] = v.w * 0.125f;
        }
    }
    if (tid < 64) {
        pidq[tid] = pids[bb * LL + i0 + tid];
        mrow[tid] = -1e30f;
        lrow[tid] = 0.f;
    }

    float O[4][4];
    #pragma unroll
    for (int i = 0; i < 4; i++)
        #pragma unroll
        for (int j = 0; j < 4; j++) O[i][j] = 0.f;

    for (int t = 0; t < 16; t++) {
        int j0 = t * 64;
        {
            int r = tid >> 2, seg = tid & 3;
            const float* ks = Km + (size_t)(bb * LL + j0 + r) * DD + h * 64 + seg * 16;
            const float* vs = Vm + (size_t)(bb * LL + j0 + r) * DD + h * 64 + seg * 16;
            #pragma unroll
            for (int u = 0; u < 4; u++) {
                float4 kv = *(const float4*)(ks + u * 4);
                int d = seg * 16 + u * 4;
                Kst[(d + 0) * 64 + r] = kv.x;
                Kst[(d + 1) * 64 + r] = kv.y;
                Kst[(d + 2) * 64 + r] = kv.z;
                Kst[(d + 3) * 64 + r] = kv.w;
                float4 vv = *(const float4*)(vs + u * 4);
                *(float4*)&Vs[r * 64 + seg * 16 + u * 4] = vv;
            }
        }
        if (tid < 64) {
            pidk[tid] = pids[bb * LL + j0 + tid];
            lexs[tid] = lex[bb * LL + j0 + tid];
        }
        __syncthreads();

        float s[4][4];
        #pragma unroll
        for (int i = 0; i < 4; i++)
            #pragma unroll
            for (int j = 0; j < 4; j++) s[i][j] = 0.f;
        #pragma unroll 8
        for (int d = 0; d < 64; d++) {
            float4 a = *(const float4*)&Kst[d * 64 + ty * 4];
            float4 wv4 = *(const float4*)&Qst[d * 64 + tx * 4];
            float av[4] = {a.x, a.y, a.z, a.w};
            float wv[4] = {wv4.x, wv4.y, wv4.z, wv4.w};
            #pragma unroll
            for (int i = 0; i < 4; i++)
                #pragma unroll
                for (int j = 0; j < 4; j++) s[i][j] += av[i] * wv[j];
        }
        #pragma unroll
        for (int i = 0; i < 4; i++) {
            int jl = ty * 4 + i;
            int jg = j0 + jl;
            int pk = pidk[jl];
            float lx = lexs[jl];
            #pragma unroll
            for (int jj = 0; jj < 4; jj++) {
                int rl = tx * 4 + jj;
                int rg = i0 + rl;
                int rel = jg - rg;
                rel = min(max(rel, -MAXD_), MAXD_);
                float pb = rel_emb[(rel + MAXD_) * HH + h];
                float pt = ptab[(pidq[rl] * PP + pk) * HH + h];
                St[jl * 68 + rl] = s[i][jj] + pb + pt + lx;
            }
        }
        __syncthreads();

        {
            float mo = mrow[lr];
            float mx = -1e30f;
            #pragma unroll
            for (int k = 0; k < 16; k++)
                mx = fmaxf(mx, St[(lq * 16 + k) * 68 + lr]);
            mx = fmaxf(mx, __shfl_xor_sync(0xffffffffu, mx, 1));
            mx = fmaxf(mx, __shfl_xor_sync(0xffffffffu, mx, 2));
            float mn = fmaxf(mo, mx);
            float a = __expf(mo - mn);
            float sum = 0.f;
            #pragma unroll
            for (int k = 0; k < 16; k++) {
                int idx = (lq * 16 + k) * 68 + lr;
                float e = __expf(St[idx] - mn);
                St[idx] = e;
                sum += e;
            }
            sum += __shfl_xor_sync(0xffffffffu, sum, 1);
            sum += __shfl_xor_sync(0xffffffffu, sum, 2);
            if (lq == 0) {
                mrow[lr] = mn;
                lrow[lr] = lrow[lr] * a + sum;
                arow[lr] = a;
            }
        }
        __syncthreads();

        #pragma unroll
        for (int i = 0; i < 4; i++) {
            float al = arow[ty * 4 + i];
            #pragma unroll
            for (int j = 0; j < 4; j++) O[i][j] *= al;
        }
        #pragma unroll 8
        for (int j = 0; j < 64; j++) {
            float4 p = *(const float4*)&St[j * 68 + ty * 4];
            float4 v = *(const float4*)&Vs[j * 64 + tx * 4];
            float pv[4] = {p.x, p.y, p.z, p.w};
            float vv[4] = {v.x, v.y, v.z, v.w};
            #pragma unroll
            for (int i = 0; i < 4; i++)
                #pragma unroll
                for (int jj = 0; jj < 4; jj++) O[i][jj] += pv[i] * vv[jj];
        }
        __syncthreads();
    }

    // ctx feeds the Wo GEMM -> round to tf32 here
    #pragma unroll
    for (int i = 0; i < 4; i++) {
        int rl = ty * 4 + i;
        float inv = 1.f / lrow[rl];
        float4 o;
        o.x = tf32r(O[i][0] * inv); o.y = tf32r(O[i][1] * inv);
        o.z = tf32r(O[i][2] * inv); o.w = tf32r(O[i][3] * inv);
        *(float4*)(ctx + (size_t)(bb * LL + i0 + rl) * DD + h * 64 + tx * 4) = o;
    }
}

// ---------------- launch ----------------
extern "C" void kernel_launch(void* const* d_in, const int* in_sizes, int n_in,
                              void* d_out, int out_size) {
    const float* x      = (const float*)d_in[0];
    const int*   postag = (const int*)  d_in[1];
    const float* lexm   = (const float*)d_in[2];
    const float* ln1g   = (const float*)d_in[3];
    const float* ln1b   = (const float*)d_in[4];
    const float* Wq     = (const float*)d_in[5];
    const float* bq     = (const float*)d_in[6];
    const float* Wk     = (const float*)d_in[7];
    const float* bk     = (const float*)d_in[8];
    const float* Wv     = (const float*)d_in[9];
    const float* bv     = (const float*)d_in[10];
    const float* Wo     = (const float*)d_in[11];
    const float* bo     = (const float*)d_in[12];
    const float* rel    = (const float*)d_in[13];
    const float* ptab   = (const float*)d_in[14];
    const float* ln2g   = (const float*)d_in[15];
    const float* ln2b   = (const float*)d_in[16];
    const float* W1     = (const float*)d_in[17];
    const float* b1     = (const float*)d_in[18];
    const float* W2     = (const float*)d_in[19];
    const float* b2     = (const float*)d_in[20];
    float* out = (float*)d_out;

    float *qin, *Qb, *Kb, *Vb, *ctx, *res1, *h2, *ff;
    float *WqT, *WkT, *WvT, *WoT, *W1T, *W2T;
    cudaGetSymbolAddress((void**)&qin,  g_qin);
    cudaGetSymbolAddress((void**)&Qb,   g_Q);
    cudaGetSymbolAddress((void**)&Kb,   g_K);
    cudaGetSymbolAddress((void**)&Vb,   g_V);
    cudaGetSymbolAddress((void**)&ctx,  g_ctx);
    cudaGetSymbolAddress((void**)&res1, g_res1);
    cudaGetSymbolAddress((void**)&h2,   g_h2);
    cudaGetSymbolAddress((void**)&ff,   g_ff);
    cudaGetSymbolAddress((void**)&WqT,  g_WqT);
    cudaGetSymbolAddress((void**)&WkT,  g_WkT);
    cudaGetSymbolAddress((void**)&WvT,  g_WvT);
    cudaGetSymbolAddress((void**)&WoT,  g_WoT);
    cudaGetSymbolAddress((void**)&W1T,  g_W1T);
    cudaGetSymbolAddress((void**)&W2T,  g_W2T);

    cudaFuncSetAttribute(attn_kernel, cudaFuncAttributeMaxDynamicSharedMemorySize, ATTN_SMEM);
    cudaFuncSetAttribute(mma_gemm<0,0>, cudaFuncAttributeMaxDynamicSharedMemorySize, GSMEM);
    cudaFuncSetAttribute(mma_gemm<1,0>, cudaFuncAttributeMaxDynamicSharedMemorySize, GSMEM);
    cudaFuncSetAttribute(mma_gemm<2,1>, cudaFuncAttributeMaxDynamicSharedMemorySize, GSMEM);

    // 0. transpose weights -> [N,K] (tf32-rounded)
    transpose_k<<<dim3(DD / 32, DD / 32), dim3(32, 8)>>>(Wq, WqT, DD, DD);
    transpose_k<<<dim3(DD / 32, DD / 32), dim3(32, 8)>>>(Wk, WkT, DD, DD);
    transpose_k<<<dim3(DD / 32, DD / 32), dim3(32, 8)>>>(Wv, WvT, DD, DD);
    transpose_k<<<dim3(DD / 32, DD / 32), dim3(32, 8)>>>(Wo, WoT, DD, DD);
    transpose_k<<<dim3(FF_ / 32, DD / 32), dim3(32, 8)>>>(W1, W1T, DD, FF_);
    transpose_k<<<dim3(DD / 32, FF_ / 32), dim3(32, 8)>>>(W2, W2T, FF_, DD);

    // 1. LN1 (tf32 out)
    ln_kernel<<<ML, 256>>>(x, ln1g, ln1b, qin, 1e-6f);
    // 2. QKV projections (mma.sync tf32)
    mma_gemm<0,0><<<dim3(DD / 128, ML / 128), 256, GSMEM>>>(qin, WqT, bq, nullptr, Qb, DD, DD);
    mma_gemm<0,0><<<dim3(DD / 128, ML / 128), 256, GSMEM>>>(qin, WkT, bk, nullptr, Kb, DD, DD);
    mma_gemm<0,0><<<dim3(DD / 128, ML / 128), 256, GSMEM>>>(qin, WvT, bv, nullptr, Vb, DD, DD);
    // 3. attention (fp32, ctx rounded to tf32)
    attn_kernel<<<dim3(LL / 64, HH, BB), 256, ATTN_SMEM>>>(Qb, Kb, Vb, rel, ptab, postag, lexm, ctx);
    // 4. output projection + residual (fp32 residual x)
    mma_gemm<1,0><<<dim3(DD / 128, ML / 128), 256, GSMEM>>>(ctx, WoT, bo, x, res1, DD, DD);
    // 5. LN2 (tf32 out)
    ln_kernel<<<ML, 256>>>(res1, ln2g, ln2b, h2, 1e-5f);
    // 6. FFN up + GELU (tf32 out for W2 A-operand)
    mma_gemm<2,1><<<dim3(FF_ / 128, ML / 128), 256, GSMEM>>>(h2, W1T, b1, nullptr, ff, DD, FF_);
    // 7. FFN down + bias + residual -> out (fp32)
    mma_gemm<1,0><<<dim3(DD / 128, ML / 128), 256, GSMEM>>>(ff, W2T, b2, res1, out, FF_, DD);
}

// round 6
// speedup vs baseline: 2.0841x; 1.4360x over previous
#include <cuda_runtime.h>
#include <math.h>
#include <stdint.h>

// Problem constants
#define BB   4
#define LL   1024
#define DD   768
#define HH   12
#define FF_  3072
#define PP   32
#define MAXD_ 256
#define ML   (BB*LL)   // 4096 rows
#define QKVS 2304      // fused QKV row stride

// ---------------- scratch (device globals; no runtime allocation) ----------
__device__ float g_qin[ML*DD];
__device__ float g_QKV[ML*QKVS];
__device__ float g_ctx[ML*DD];
__device__ float g_res1[ML*DD];
__device__ float g_h2[ML*DD];
__device__ float g_ff[ML*FF_];
// transposed weights [N,K] (tf32-rounded)
__device__ float g_WqkvT[QKVS*DD];
__device__ float g_bqkv[QKVS];
__device__ float g_WoT[DD*DD];
__device__ float g_W1T[FF_*DD];
__device__ float g_W2T[DD*FF_];

// single extern shared symbol for all kernels
extern __shared__ char smem_raw[];

// ======================= helpers =====================
__device__ __forceinline__ uint32_t smem_u32(const void* p) {
    uint32_t a;
    asm("{ .reg .u64 t; cvta.to.shared.u64 t, %1; cvt.u32.u64 %0, t; }" : "=r"(a) : "l"(p));
    return a;
}
__device__ __forceinline__ uint32_t f2tf32(float f) {
    uint32_t o; asm("cvt.rna.tf32.f32 %0, %1;" : "=r"(o) : "f"(f)); return o;
}
__device__ __forceinline__ float tf32r(float f) {
    return __uint_as_float(f2tf32(f));
}

#define CP_ASYNC16(dst, src) \
    asm volatile("cp.async.ca.shared.global [%0], [%1], 16;" :: "r"(dst), "l"(src) : "memory")
#define CP_COMMIT()  asm volatile("cp.async.commit_group;" ::: "memory")
#define CP_WAIT1()   asm volatile("cp.async.wait_group 1;" ::: "memory")

__device__ __forceinline__ void mma_tf32(float c[4], uint32_t a0, uint32_t a1,
                                         uint32_t a2, uint32_t a3,
                                         uint32_t b0, uint32_t b1) {
    asm volatile(
        "mma.sync.aligned.m16n8k8.row.col.f32.tf32.tf32.f32 "
        "{%0,%1,%2,%3}, {%4,%5,%6,%7}, {%8,%9}, {%0,%1,%2,%3};"
        : "+f"(c[0]), "+f"(c[1]), "+f"(c[2]), "+f"(c[3])
        : "r"(a0), "r"(a1), "r"(a2), "r"(a3), "r"(b0), "r"(b1));
}

// ---------------- fused QKV weight transpose + bias concat ----------------
// z = 0/1/2 selects Wq/Wk/Wv; writes [z*768 + n][k] into WT; copies bias.
__global__ void transpose_qkv(const float* __restrict__ Wq, const float* __restrict__ Wk,
                              const float* __restrict__ Wv, const float* __restrict__ bq,
                              const float* __restrict__ bk, const float* __restrict__ bv,
                              float* __restrict__ WT, float* __restrict__ bqkv) {
    __shared__ float t[32][33];
    int z = blockIdx.z;
    const float* src = (z == 0) ? Wq : (z == 1) ? Wk : Wv;
    int c0 = blockIdx.x * 32, r0 = blockIdx.y * 32;
    int x = threadIdx.x, y = threadIdx.y;
    #pragma unroll
    for (int i = 0; i < 32; i += 8)
        t[y + i][x] = src[(size_t)(r0 + y + i) * DD + c0 + x];
    __syncthreads();
    #pragma unroll
    for (int i = 0; i < 32; i += 8)
        WT[(size_t)(z * DD + c0 + y + i) * DD + r0 + x] = tf32r(t[x][y + i]);
    if (blockIdx.x == 0 && blockIdx.y == 0) {
        const float* bsrc = (z == 0) ? bq : (z == 1) ? bk : bv;
        int tid = y * 32 + x;
        for (int i = tid; i < DD; i += 256) bqkv[z * DD + i] = bsrc[i];
    }
}

// ---------------- generic weight transpose: dst[N,K] = src[K,N] -----------
__global__ void transpose_k(const float* __restrict__ src, float* __restrict__ dst,
                            int R, int C) {
    __shared__ float t[32][33];
    int c0 = blockIdx.x * 32, r0 = blockIdx.y * 32;
    int x = threadIdx.x, y = threadIdx.y;
    #pragma unroll
    for (int i = 0; i < 32; i += 8)
        t[y + i][x] = src[(size_t)(r0 + y + i) * C + c0 + x];
    __syncthreads();
    #pragma unroll
    for (int i = 0; i < 32; i += 8)
        dst[(size_t)(c0 + y + i) * R + r0 + x] = tf32r(t[x][y + i]);
}

// ---------------- LayerNorm (tf32-rounded output) ----------------
__global__ void ln_kernel(const float* __restrict__ x, const float* __restrict__ g,
                          const float* __restrict__ b, float* __restrict__ y, float eps) {
    int row = blockIdx.x;
    const float* xr = x + (size_t)row * DD;
    __shared__ float red[256];
    int tid = threadIdx.x;

    float s = 0.f;
    for (int d = tid; d < DD; d += 256) s += xr[d];
    red[tid] = s; __syncthreads();
    #pragma unroll
    for (int o = 128; o > 0; o >>= 1) { if (tid < o) red[tid] += red[tid + o]; __syncthreads(); }
    float mu = red[0] * (1.f / DD);
    __syncthreads();

    float v = 0.f;
    for (int d = tid; d < DD; d += 256) { float t = xr[d] - mu; v += t * t; }
    red[tid] = v; __syncthreads();
    #pragma unroll
    for (int o = 128; o > 0; o >>= 1) { if (tid < o) red[tid] += red[tid + o]; __syncthreads(); }
    float inv = rsqrtf(red[0] * (1.f / DD) + eps);

    float* yr = y + (size_t)row * DD;
    for (int d = tid; d < DD; d += 256)
        yr[d] = tf32r((xr[d] - mu) * inv * g[d] + b[d]);
}

// ============ mma.sync tf32 GEMM: C[M,N] = A[M,K] @ Bt[N,K]^T + epi ========
#define NSTAGE 3
#define GSMEM (NSTAGE * 2 * 4096 * 4)   // 98304 bytes

template<int EPI, int TF32OUT>
__global__ __launch_bounds__(256) void mma_gemm(
    const float* __restrict__ A, const float* __restrict__ Bt,
    const float* __restrict__ bias, const float* __restrict__ res,
    float* __restrict__ C, int K, int N) {
    float* sm = (float*)smem_raw;
    uint32_t smem_base = smem_u32(sm);

    int tid = threadIdx.x;
    int wid = tid >> 5, lane = tid & 31;
    int r = lane >> 2, l = lane & 3;
    int row0 = blockIdx.y * 128, col0 = blockIdx.x * 128;
    int m0 = (wid & 3) * 32, n0 = (wid >> 2) * 64;

    int qq = tid & 7;
    int mm = tid >> 3;
    const float* srcA = A + (size_t)(row0 + mm) * K + qq * 4;
    const float* srcB = Bt + (size_t)(col0 + mm) * K + qq * 4;
    uint32_t dA0 = smem_base + (qq * 512 + mm * 4) * 4;
    uint32_t dB0 = dA0 + 16384;

    int nc = K >> 5;

    float acc[2][8][4];
    #pragma unroll
    for (int i = 0; i < 2; i++)
        #pragma unroll
        for (int j = 0; j < 8; j++)
            #pragma unroll
            for (int k = 0; k < 4; k++) acc[i][j][k] = 0.f;

    #pragma unroll
    for (int s = 0; s < NSTAGE - 1; s++) {
        uint32_t so = s * 32768;
        #pragma unroll
        for (int u = 0; u < 4; u++) {
            CP_ASYNC16(dA0 + so + u * 512, srcA + (size_t)(s * 32) + (size_t)u * 32 * K);
            CP_ASYNC16(dB0 + so + u * 512, srcB + (size_t)(s * 32) + (size_t)u * 32 * K);
        }
        CP_COMMIT();
    }

    for (int c = 0; c < nc; c++) {
        CP_WAIT1();
        __syncthreads();
        int nstg = c + NSTAGE - 1;
        if (nstg < nc) {
            uint32_t so = (nstg % NSTAGE) * 32768;
            #pragma unroll
            for (int u = 0; u < 4; u++) {
                CP_ASYNC16(dA0 + so + u * 512, srcA + (size_t)(nstg * 32) + (size_t)u * 32 * K);
                CP_ASYNC16(dB0 + so + u * 512, srcB + (size_t)(nstg * 32) + (size_t)u * 32 * K);
            }
        }
        CP_COMMIT();

        const float* sA = sm + (c % NSTAGE) * 8192;
        const float* sB = sA + 4096;
        #pragma unroll
        for (int ks = 0; ks < 4; ks++) {
            int kb = ks * 1024;
            uint32_t a[2][4];
            #pragma unroll
            for (int mi = 0; mi < 2; mi++) {
                int ao = kb + (m0 + 16 * mi + r) * 4 + l;
                a[mi][0] = __float_as_uint(sA[ao]);
                a[mi][1] = __float_as_uint(sA[ao + 32]);
                a[mi][2] = __float_as_uint(sA[ao + 512]);
                a[mi][3] = __float_as_uint(sA[ao + 544]);
            }
            #pragma unroll
            for (int nj = 0; nj < 8; nj++) {
                int bo = kb + (n0 + 8 * nj + r) * 4 + l;
                uint32_t b0 = __float_as_uint(sB[bo]);
                uint32_t b1 = __float_as_uint(sB[bo + 512]);
                mma_tf32(acc[0][nj], a[0][0], a[0][1], a[0][2], a[0][3], b0, b1);
                mma_tf32(acc[1][nj], a[1][0], a[1][1], a[1][2], a[1][3], b0, b1);
            }
        }
    }

    #pragma unroll
    for (int mi = 0; mi < 2; mi++) {
        int rr = row0 + m0 + 16 * mi + r;
        #pragma unroll
        for (int nj = 0; nj < 8; nj++) {
            int cc = col0 + n0 + 8 * nj + 2 * l;
            float b0 = bias[cc], b1 = bias[cc + 1];
            float v0 = acc[mi][nj][0] + b0;
            float v1 = acc[mi][nj][1] + b1;
            float v2 = acc[mi][nj][2] + b0;
            float v3 = acc[mi][nj][3] + b1;
            if (EPI == 1) {
                const float* rp0 = res + (size_t)rr * N + cc;
                const float* rp1 = res + (size_t)(rr + 8) * N + cc;
                v0 += rp0[0]; v1 += rp0[1];
                v2 += rp1[0]; v3 += rp1[1];
            }
            if (EPI == 2) {
                v0 = 0.5f * v0 * (1.f + erff(v0 * 0.70710678118654752f));
                v1 = 0.5f * v1 * (1.f + erff(v1 * 0.70710678118654752f));
                v2 = 0.5f * v2 * (1.f + erff(v2 * 0.70710678118654752f));
                v3 = 0.5f * v3 * (1.f + erff(v3 * 0.70710678118654752f));
            }
            if (TF32OUT) {
                v0 = tf32r(v0); v1 = tf32r(v1); v2 = tf32r(v2); v3 = tf32r(v3);
            }
            float2 o01 = { v0, v1 };
            float2 o23 = { v2, v3 };
            *(float2*)(C + (size_t)rr * N + cc) = o01;
            *(float2*)(C + (size_t)(rr + 8) * N + cc) = o23;
        }
    }
}

// ================= tensor-core flash attention (tf32 mma) ==================
// CTA: 128-query tile x head x batch. 8 warps; warp = 16 rows x 64 cols.
// smem float offsets:
#define AT_QS   0            // [128][68]
#define AT_KS   8704         // [64][68]   K tile [j][d]
#define AT_VT   13056        // [64][68]   V^T tile [d][j]
#define AT_PS   17408        // [128][68]  probs
#define AT_RELS 26112        // [513]
#define AT_PTS  26625        // [1024]
#define AT_LEX  27649        // [64]
#define AT_MROW 27713        // [128]
#define AT_LROW 27841        // [128]
#define AT_PIDQ 27969        // [128] int
#define AT_PIDK 28097        // [64]  int
#define AT_TOT  28161
#define ATTN_SMEM (AT_TOT * 4)

__global__ __launch_bounds__(256) void attn_mma(
    const float* __restrict__ QKV, const float* __restrict__ rel_emb,
    const float* __restrict__ ptab, const int* __restrict__ pids,
    const float* __restrict__ lex, float* __restrict__ ctx) {
    float* sm = (float*)smem_raw;
    int* smi = (int*)smem_raw;
    const float LOG2E = 1.44269504089f;

    int tid = threadIdx.x;
    int w = tid >> 5, lane = tid & 31;
    int r = lane >> 2, l = lane & 3;
    int h = blockIdx.y, bbx = blockIdx.z;
    int i0 = blockIdx.x * 128;

    // tables for this head
    for (int i = tid; i < 513; i += 256) sm[AT_RELS + i] = rel_emb[i * HH + h];
    for (int i = tid; i < 1024; i += 256) sm[AT_PTS + i] = ptab[i * HH + h];
    if (tid < 128) {
        smi[AT_PIDQ + tid] = pids[bbx * LL + i0 + tid];
        sm[AT_MROW + tid] = -1e30f;
        sm[AT_LROW + tid] = 0.f;
    }
    // Q tile (scaled by 1/8, tf32)
    {
        int row = tid >> 1, dh = (tid & 1) * 32;
        const float* src = QKV + (size_t)(bbx * LL + i0 + row) * QKVS + h * 64 + dh;
        #pragma unroll
        for (int u = 0; u < 8; u++) {
            float4 v = *(const float4*)(src + u * 4);
            uint4 t = { f2tf32(v.x * 0.125f), f2tf32(v.y * 0.125f),
                        f2tf32(v.z * 0.125f), f2tf32(v.w * 0.125f) };
            *(uint4*)&sm[AT_QS + row * 68 + dh + u * 4] = t;
        }
    }
    __syncthreads();

    // Q fragments resident in registers
    uint32_t aq[8][4];
    {
        int m = w * 16 + r;
        #pragma unroll
        for (int kk = 0; kk < 8; kk++) {
            aq[kk][0] = __float_as_uint(sm[AT_QS + m * 68 + kk * 8 + l]);
            aq[kk][1] = __float_as_uint(sm[AT_QS + (m + 8) * 68 + kk * 8 + l]);
            aq[kk][2] = __float_as_uint(sm[AT_QS + m * 68 + kk * 8 + l + 4]);
            aq[kk][3] = __float_as_uint(sm[AT_QS + (m + 8) * 68 + kk * 8 + l + 4]);
        }
    }
    int pq0 = smi[AT_PIDQ + w * 16 + r] * PP;
    int pq1 = smi[AT_PIDQ + w * 16 + r + 8] * PP;

    float o[8][4];
    #pragma unroll
    for (int nj = 0; nj < 8; nj++)
        #pragma unroll
        for (int k = 0; k < 4; k++) o[nj][k] = 0.f;

    for (int t = 0; t < 16; t++) {
        int j0 = t * 64;
        // load K -> Ks[j][d], V -> Vt[d][j] (tf32)
        {
            int j = tid >> 2, dseg = tid & 3;
            const float* ksrc = QKV + (size_t)(bbx * LL + j0 + j) * QKVS + 768 + h * 64 + dseg * 16;
            const float* vsrc = ksrc + 768;
            #pragma unroll
            for (int u = 0; u < 4; u++) {
                float4 kv = *(const float4*)(ksrc + u * 4);
                uint4 kt = { f2tf32(kv.x), f2tf32(kv.y), f2tf32(kv.z), f2tf32(kv.w) };
                *(uint4*)&sm[AT_KS + j * 68 + dseg * 16 + u * 4] = kt;
                float4 vv = *(const float4*)(vsrc + u * 4);
                int d = dseg * 16 + u * 4;
                sm[AT_VT + (d + 0) * 68 + j] = tf32r(vv.x);
                sm[AT_VT + (d + 1) * 68 + j] = tf32r(vv.y);
                sm[AT_VT + (d + 2) * 68 + j] = tf32r(vv.z);
                sm[AT_VT + (d + 3) * 68 + j] = tf32r(vv.w);
            }
        }
        if (tid < 64) {
            smi[AT_PIDK + tid] = pids[bbx * LL + j0 + tid];
            sm[AT_LEX + tid] = lex[bbx * LL + j0 + tid];
        }
        __syncthreads();

        // S = Q @ K^T
        float s[8][4];
        #pragma unroll
        for (int nj = 0; nj < 8; nj++)
            #pragma unroll
            for (int k = 0; k < 4; k++) s[nj][k] = 0.f;
        #pragma unroll
        for (int kk = 0; kk < 8; kk++) {
            #pragma unroll
            for (int nj = 0; nj < 8; nj++) {
                uint32_t b0 = __float_as_uint(sm[AT_KS + (nj * 8 + r) * 68 + kk * 8 + l]);
                uint32_t b1 = __float_as_uint(sm[AT_KS + (nj * 8 + r) * 68 + kk * 8 + l + 4]);
                mma_tf32(s[nj], aq[kk][0], aq[kk][1], aq[kk][2], aq[kk][3], b0, b1);
            }
        }

        // biases + row max
        int rg0 = i0 + w * 16 + r, rg1 = rg0 + 8;
        float mx0 = -1e30f, mx1 = -1e30f;
        #pragma unroll
        for (int nj = 0; nj < 8; nj++) {
            int ca = nj * 8 + 2 * l;
            int jga = j0 + ca;
            int pka = smi[AT_PIDK + ca], pkb = smi[AT_PIDK + ca + 1];
            float lxa = sm[AT_LEX + ca], lxb = sm[AT_LEX + ca + 1];
            int ra0 = min(max(jga - rg0, -MAXD_), MAXD_) + MAXD_;
            int rb0 = min(max(jga + 1 - rg0, -MAXD_), MAXD_) + MAXD_;
            int ra1 = min(max(jga - rg1, -MAXD_), MAXD_) + MAXD_;
            int rb1 = min(max(jga + 1 - rg1, -MAXD_), MAXD_) + MAXD_;
            s[nj][0] += sm[AT_RELS + ra0] + sm[AT_PTS + pq0 + pka] + lxa;
            s[nj][1] += sm[AT_RELS + rb0] + sm[AT_PTS + pq0 + pkb] + lxb;
            s[nj][2] += sm[AT_RELS + ra1] + sm[AT_PTS + pq1 + pka] + lxa;
            s[nj][3] += sm[AT_RELS + rb1] + sm[AT_PTS + pq1 + pkb] + lxb;
            mx0 = fmaxf(mx0, fmaxf(s[nj][0], s[nj][1]));
            mx1 = fmaxf(mx1, fmaxf(s[nj][2], s[nj][3]));
        }
        mx0 = fmaxf(mx0, __shfl_xor_sync(0xffffffffu, mx0, 1));
        mx0 = fmaxf(mx0, __shfl_xor_sync(0xffffffffu, mx0, 2));
        mx1 = fmaxf(mx1, __shfl_xor_sync(0xffffffffu, mx1, 1));
        mx1 = fmaxf(mx1, __shfl_xor_sync(0xffffffffu, mx1, 2));

        float mo0 = sm[AT_MROW + w * 16 + r], mo1 = sm[AT_MROW + w * 16 + r + 8];
        float mn0 = fmaxf(mo0, mx0), mn1 = fmaxf(mo1, mx1);
        float al0 = exp2f((mo0 - mn0) * LOG2E), al1 = exp2f((mo1 - mn1) * LOG2E);
        float sum0 = 0.f, sum1 = 0.f;
        #pragma unroll
        for (int nj = 0; nj < 8; nj++) {
            float p0 = exp2f((s[nj][0] - mn0) * LOG2E);
            float p1 = exp2f((s[nj][1] - mn0) * LOG2E);
            float p2 = exp2f((s[nj][2] - mn1) * LOG2E);
            float p3 = exp2f((s[nj][3] - mn1) * LOG2E);
            sum0 += p0 + p1; sum1 += p2 + p3;
            float2 q01 = { p0, p1 };
            float2 q23 = { p2, p3 };
            *(float2*)&sm[AT_PS + (w * 16 + r) * 68 + nj * 8 + 2 * l] = q01;
            *(float2*)&sm[AT_PS + (w * 16 + r + 8) * 68 + nj * 8 + 2 * l] = q23;
            o[nj][0] *= al0; o[nj][1] *= al0; o[nj][2] *= al1; o[nj][3] *= al1;
        }
        sum0 += __shfl_xor_sync(0xffffffffu, sum0, 1);
        sum0 += __shfl_xor_sync(0xffffffffu, sum0, 2);
        sum1 += __shfl_xor_sync(0xffffffffu, sum1, 1);
        sum1 += __shfl_xor_sync(0xffffffffu, sum1, 2);
        if (l == 0) {
            sm[AT_MROW + w * 16 + r] = mn0;
            sm[AT_MROW + w * 16 + r + 8] = mn1;
            sm[AT_LROW + w * 16 + r] = sm[AT_LROW + w * 16 + r] * al0 + sum0;
            sm[AT_LROW + w * 16 + r + 8] = sm[AT_LROW + w * 16 + r + 8] * al1 + sum1;
        }
        __syncwarp();

        // O += P @ V
        #pragma unroll
        for (int kk = 0; kk < 8; kk++) {
            uint32_t ap0 = __float_as_uint(sm[AT_PS + (w * 16 + r) * 68 + kk * 8 + l]);
            uint32_t ap1 = __float_as_uint(sm[AT_PS + (w * 16 + r + 8) * 68 + kk * 8 + l]);
            uint32_t ap2 = __float_as_uint(sm[AT_PS + (w * 16 + r) * 68 + kk * 8 + l + 4]);
            uint32_t ap3 = __float_as_uint(sm[AT_PS + (w * 16 + r + 8) * 68 + kk * 8 + l + 4]);
            #pragma unroll
            for (int nj = 0; nj < 8; nj++) {
                uint32_t b0 = __float_as_uint(sm[AT_VT + (nj * 8 + r) * 68 + kk * 8 + l]);
                uint32_t b1 = __float_as_uint(sm[AT_VT + (nj * 8 + r) * 68 + kk * 8 + l + 4]);
                mma_tf32(o[nj], ap0, ap1, ap2, ap3, b0, b1);
            }
        }
        __syncthreads();
    }

    // finalize: divide by l, write ctx (tf32 for Wo gemm)
    float inv0 = 1.f / sm[AT_LROW + w * 16 + r];
    float inv1 = 1.f / sm[AT_LROW + w * 16 + r + 8];
    int row0g = bbx * LL + i0 + w * 16 + r;
    #pragma unroll
    for (int nj = 0; nj < 8; nj++) {
        float2 v0 = { tf32r(o[nj][0] * inv0), tf32r(o[nj][1] * inv0) };
        float2 v1 = { tf32r(o[nj][2] * inv1), tf32r(o[nj][3] * inv1) };
        *(float2*)(ctx + (size_t)row0g * DD + h * 64 + nj * 8 + 2 * l) = v0;
        *(float2*)(ctx + (size_t)(row0g + 8) * DD + h * 64 + nj * 8 + 2 * l) = v1;
    }
}

// ---------------- launch ----------------
extern "C" void kernel_launch(void* const* d_in, const int* in_sizes, int n_in,
                              void* d_out, int out_size) {
    const float* x      = (const float*)d_in[0];
    const int*   postag = (const int*)  d_in[1];
    const float* lexm   = (const float*)d_in[2];
    const float* ln1g   = (const float*)d_in[3];
    const float* ln1b   = (const float*)d_in[4];
    const float* Wq     = (const float*)d_in[5];
    const float* bq     = (const float*)d_in[6];
    const float* Wk     = (const float*)d_in[7];
    const float* bk     = (const float*)d_in[8];
    const float* Wv     = (const float*)d_in[9];
    const float* bv     = (const float*)d_in[10];
    const float* Wo     = (const float*)d_in[11];
    const float* bo     = (const float*)d_in[12];
    const float* rel    = (const float*)d_in[13];
    const float* ptab   = (const float*)d_in[14];
    const float* ln2g   = (const float*)d_in[15];
    const float* ln2b   = (const float*)d_in[16];
    const float* W1     = (const float*)d_in[17];
    const float* b1     = (const float*)d_in[18];
    const float* W2     = (const float*)d_in[19];
    const float* b2     = (const float*)d_in[20];
    float* out = (float*)d_out;

    float *qin, *QKVb, *ctx, *res1, *h2, *ff;
    float *WqkvT, *bqkv, *WoT, *W1T, *W2T;
    cudaGetSymbolAddress((void**)&qin,   g_qin);
    cudaGetSymbolAddress((void**)&QKVb,  g_QKV);
    cudaGetSymbolAddress((void**)&ctx,   g_ctx);
    cudaGetSymbolAddress((void**)&res1,  g_res1);
    cudaGetSymbolAddress((void**)&h2,    g_h2);
    cudaGetSymbolAddress((void**)&ff,    g_ff);
    cudaGetSymbolAddress((void**)&WqkvT, g_WqkvT);
    cudaGetSymbolAddress((void**)&bqkv,  g_bqkv);
    cudaGetSymbolAddress((void**)&WoT,   g_WoT);
    cudaGetSymbolAddress((void**)&W1T,   g_W1T);
    cudaGetSymbolAddress((void**)&W2T,   g_W2T);

    cudaFuncSetAttribute(attn_mma, cudaFuncAttributeMaxDynamicSharedMemorySize, ATTN_SMEM);
    cudaFuncSetAttribute(mma_gemm<0,0>, cudaFuncAttributeMaxDynamicSharedMemorySize, GSMEM);
    cudaFuncSetAttribute(mma_gemm<1,0>, cudaFuncAttributeMaxDynamicSharedMemorySize, GSMEM);
    cudaFuncSetAttribute(mma_gemm<2,1>, cudaFuncAttributeMaxDynamicSharedMemorySize, GSMEM);

    // 0: fused QKV weight transpose + bias concat
    transpose_qkv<<<dim3(DD / 32, DD / 32, 3), dim3(32, 8)>>>(Wq, Wk, Wv, bq, bk, bv, WqkvT, bqkv);
    // 1-3: remaining transposes
    transpose_k<<<dim3(DD / 32, DD / 32), dim3(32, 8)>>>(Wo, WoT, DD, DD);
    transpose_k<<<dim3(FF_ / 32, DD / 32), dim3(32, 8)>>>(W1, W1T, DD, FF_);
    transpose_k<<<dim3(DD / 32, FF_ / 32), dim3(32, 8)>>>(W2, W2T, FF_, DD);
    // 4: LN1
    ln_kernel<<<ML, 256>>>(x, ln1g, ln1b, qin, 1e-6f);
    // 5: fused QKV projection  (ncu -s 5 captures this)
    mma_gemm<0,0><<<dim3(QKVS / 128, ML / 128), 256, GSMEM>>>(qin, WqkvT, bqkv, nullptr, QKVb, DD, QKVS);
    // 6: tensor-core attention
    attn_mma<<<dim3(LL / 128, HH, BB), 256, ATTN_SMEM>>>(QKVb, rel, ptab, postag, lexm, ctx);
    // 7: output projection + residual
    mma_gemm<1,0><<<dim3(DD / 128, ML / 128), 256, GSMEM>>>(ctx, WoT, bo, x, res1, DD, DD);
    // 8: LN2
    ln_kernel<<<ML, 256>>>(res1, ln2g, ln2b, h2, 1e-5f);
    // 9: FFN up + GELU
    mma_gemm<2,1><<<dim3(FF_ / 128, ML / 128), 256, GSMEM>>>(h2, W1T, b1, nullptr, ff, DD, FF_);
    // 10: FFN down + bias + residual -> out
    mma_gemm<1,0><<<dim3(DD / 128, ML / 128), 256, GSMEM>>>(ff, W2T, b2, res1, out, FF_, DD);
}

// round 7
// speedup vs baseline: 3.4738x; 1.6668x over previous
#include <cuda_runtime.h>
#include <math.h>
#include <stdint.h>

// Problem constants
#define BB   4
#define LL   1024
#define DD   768
#define HH   12
#define FF_  3072
#define PP   32
#define MAXD_ 256
#define ML   (BB*LL)   // 4096 rows
#define QKVS 2304      // fused QKV row stride

// ---------------- scratch (device globals; no runtime allocation) ----------
__device__ float g_qin[ML*DD];
__device__ float g_QKV[ML*QKVS];
__device__ float g_ctx[ML*DD];
__device__ float g_res1[ML*DD];
__device__ float g_h2[ML*DD];
__device__ float g_ff[ML*FF_];
// transposed weights [N,K] (tf32-rounded)
__device__ float g_WqkvT[QKVS*DD];
__device__ float g_bqkv[QKVS];
__device__ float g_WoT[DD*DD];
__device__ float g_W1T[FF_*DD];
__device__ float g_W2T[DD*FF_];

// single extern shared symbol for all kernels
extern __shared__ char smem_raw[];

// ======================= helpers =====================
__device__ __forceinline__ uint32_t smem_u32(const void* p) {
    uint32_t a;
    asm("{ .reg .u64 t; cvta.to.shared.u64 t, %1; cvt.u32.u64 %0, t; }" : "=r"(a) : "l"(p));
    return a;
}
__device__ __forceinline__ uint32_t f2tf32(float f) {
    uint32_t o; asm("cvt.rna.tf32.f32 %0, %1;" : "=r"(o) : "f"(f)); return o;
}
__device__ __forceinline__ float tf32r(float f) {
    return __uint_as_float(f2tf32(f));
}

#define CP_ASYNC16(dst, src) \
    asm volatile("cp.async.ca.shared.global [%0], [%1], 16;" :: "r"(dst), "l"(src) : "memory")
#define CP_COMMIT()  asm volatile("cp.async.commit_group;" ::: "memory")
#define CP_WAIT1()   asm volatile("cp.async.wait_group 1;" ::: "memory")

__device__ __forceinline__ void mma_tf32(float c[4], uint32_t a0, uint32_t a1,
                                         uint32_t a2, uint32_t a3,
                                         uint32_t b0, uint32_t b1) {
    asm volatile(
        "mma.sync.aligned.m16n8k8.row.col.f32.tf32.tf32.f32 "
        "{%0,%1,%2,%3}, {%4,%5,%6,%7}, {%8,%9}, {%0,%1,%2,%3};"
        : "+f"(c[0]), "+f"(c[1]), "+f"(c[2]), "+f"(c[3])
        : "r"(a0), "r"(a1), "r"(a2), "r"(a3), "r"(b0), "r"(b1));
}
__device__ __forceinline__ void ldsm4(uint32_t r[4], uint32_t addr) {
    asm volatile("ldmatrix.sync.aligned.m8n8.x4.shared.b16 {%0,%1,%2,%3}, [%4];"
                 : "=r"(r[0]), "=r"(r[1]), "=r"(r[2]), "=r"(r[3]) : "r"(addr));
}

// ---------------- all weight transposes in ONE launch ----------------------
// blocks: [0,1728) Wq/Wk/Wv -> WqkvT, [1728,2304) Wo, [2304,4608) W1, [4608,6912) W2
__global__ void transpose_all(const float* __restrict__ Wq, const float* __restrict__ Wk,
                              const float* __restrict__ Wv, const float* __restrict__ Wo,
                              const float* __restrict__ W1, const float* __restrict__ W2,
                              const float* __restrict__ bq, const float* __restrict__ bk,
                              const float* __restrict__ bv,
                              float* __restrict__ WqkvT, float* __restrict__ bqkv,
                              float* __restrict__ WoT, float* __restrict__ W1T,
                              float* __restrict__ W2T) {
    __shared__ float t[32][33];
    int idx = blockIdx.x;
    const float* src; float* dst; int R, C, bx, by; size_t dstoff = 0;
    if (idx < 1728) {
        int z = idx / 576, lo = idx % 576;
        src = (z == 0) ? Wq : (z == 1) ? Wk : Wv;
        dst = WqkvT; R = DD; C = DD; bx = lo % 24; by = lo / 24;
        dstoff = (size_t)z * DD * DD;
    } else if (idx < 2304) {
        int lo = idx - 1728; src = Wo; dst = WoT; R = DD; C = DD; bx = lo % 24; by = lo / 24;
    } else if (idx < 4608) {
        int lo = idx - 2304; src = W1; dst = W1T; R = DD; C = FF_; bx = lo % 96; by = lo / 96;
    } else {
        int lo = idx - 4608; src = W2; dst = W2T; R = FF_; C = DD; bx = lo % 24; by = lo / 24;
    }
    int c0 = bx * 32, r0 = by * 32;
    int x = threadIdx.x, y = threadIdx.y;
    #pragma unroll
    for (int i = 0; i < 32; i += 8)
        t[y + i][x] = src[(size_t)(r0 + y + i) * C + c0 + x];
    __syncthreads();
    #pragma unroll
    for (int i = 0; i < 32; i += 8)
        dst[dstoff + (size_t)(c0 + y + i) * R + r0 + x] = tf32r(t[x][y + i]);
    if (idx == 0) {
        int tid = y * 32 + x;
        for (int i = tid; i < QKVS; i += 256)
            bqkv[i] = (i < 768) ? bq[i] : (i < 1536) ? bk[i - 768] : bv[i - 1536];
    }
}

// ---------------- LayerNorm (tf32-rounded output) ----------------
__global__ void ln_kernel(const float* __restrict__ x, const float* __restrict__ g,
                          const float* __restrict__ b, float* __restrict__ y, float eps) {
    int row = blockIdx.x;
    const float* xr = x + (size_t)row * DD;
    __shared__ float red[256];
    int tid = threadIdx.x;

    float s = 0.f;
    for (int d = tid; d < DD; d += 256) s += xr[d];
    red[tid] = s; __syncthreads();
    #pragma unroll
    for (int o = 128; o > 0; o >>= 1) { if (tid < o) red[tid] += red[tid + o]; __syncthreads(); }
    float mu = red[0] * (1.f / DD);
    __syncthreads();

    float v = 0.f;
    for (int d = tid; d < DD; d += 256) { float t = xr[d] - mu; v += t * t; }
    red[tid] = v; __syncthreads();
    #pragma unroll
    for (int o = 128; o > 0; o >>= 1) { if (tid < o) red[tid] += red[tid + o]; __syncthreads(); }
    float inv = rsqrtf(red[0] * (1.f / DD) + eps);

    float* yr = y + (size_t)row * DD;
    for (int d = tid; d < DD; d += 256)
        yr[d] = tf32r((xr[d] - mu) * inv * g[d] + b[d]);
}

// ====== mma.sync tf32 GEMM with ldmatrix fragments =========================
// C[M,N] = A[M,K] @ Bt[N,K]^T + epi.  128x128 CTA tile, 8 warps (32x64 each),
// 3-stage cp.async, K-chunk 32.
// SMEM per stage: A[128][32] swizzled rows of 128B (16KB), B same.
// byte(m, k) = m*128 + (((k>>2) ^ (m&7))<<4) + (k&3)*4
#define NSTAGE 3
#define GSMEM (NSTAGE * 32768)   // 98304 bytes

template<int EPI, int TF32OUT>
__global__ __launch_bounds__(256, 2) void mma_gemm(
    const float* __restrict__ A, const float* __restrict__ Bt,
    const float* __restrict__ bias, const float* __restrict__ res,
    float* __restrict__ C, int K, int N) {
    uint32_t smem_base = smem_u32(smem_raw);

    int tid = threadIdx.x;
    int wid = tid >> 5, lane = tid & 31;
    int r = lane >> 2, l = lane & 3;
    int quad = lane >> 3, qr = lane & 7;
    int row0 = blockIdx.y * 128, col0 = blockIdx.x * 128;
    int m0 = (wid & 3) * 32, n0 = (wid >> 2) * 64;

    // ---- loader mapping: thread -> (m_l, s_l) 16B segment
    int m_l = tid >> 3, s_l = tid & 7;
    const float* srcA = A + (size_t)(row0 + m_l) * K + s_l * 4;
    const float* srcB = Bt + (size_t)(col0 + m_l) * K + s_l * 4;
    uint32_t dA0 = smem_base + m_l * 128 + ((s_l ^ (m_l & 7)) << 4);
    uint32_t dB0 = dA0 + 16384;

    // ---- ldmatrix per-thread static addresses
    // A frag (mi): rows m0+16mi + (quad&1)*8 + qr, seg 2ks + (quad>>1)
    int rowA = m0 + ((quad & 1) << 3) + qr;
    int xA = rowA & 7, qhA = quad >> 1;
    uint32_t baseA = smem_base + rowA * 128;
    // B frags (p): rows n0+16p + (quad>>1)*8 + qr, seg 2ks + (quad&1)
    int rowB = n0 + ((quad >> 1) << 3) + qr;
    int xB = rowB & 7, qhB = quad & 1;
    uint32_t baseB = smem_base + 16384 + rowB * 128;

    int nc = K >> 5;

    float acc[2][8][4];
    #pragma unroll
    for (int i = 0; i < 2; i++)
        #pragma unroll
        for (int j = 0; j < 8; j++)
            #pragma unroll
            for (int k = 0; k < 4; k++) acc[i][j][k] = 0.f;

    // prologue
    #pragma unroll
    for (int s = 0; s < NSTAGE - 1; s++) {
        uint32_t so = s * 32768;
        #pragma unroll
        for (int u = 0; u < 4; u++) {
            CP_ASYNC16(dA0 + so + u * 4096, srcA + (size_t)(s * 32) + (size_t)u * 32 * K);
            CP_ASYNC16(dB0 + so + u * 4096, srcB + (size_t)(s * 32) + (size_t)u * 32 * K);
        }
        CP_COMMIT();
    }

    for (int c = 0; c < nc; c++) {
        CP_WAIT1();
        __syncthreads();
        int nstg = c + NSTAGE - 1;
        if (nstg < nc) {
            uint32_t so = (nstg % NSTAGE) * 32768;
            #pragma unroll
            for (int u = 0; u < 4; u++) {
                CP_ASYNC16(dA0 + so + u * 4096, srcA + (size_t)(nstg * 32) + (size_t)u * 32 * K);
                CP_ASYNC16(dB0 + so + u * 4096, srcB + (size_t)(nstg * 32) + (size_t)u * 32 * K);
            }
        }
        CP_COMMIT();

        uint32_t so = (c % NSTAGE) * 32768;
        #pragma unroll
        for (int ks = 0; ks < 4; ks++) {
            uint32_t a0[4], a1[4];
            ldsm4(a0, baseA + so + (((2 * ks + qhA) ^ xA) << 4));
            ldsm4(a1, baseA + so + 2048 + (((2 * ks + qhA) ^ xA) << 4));
            #pragma unroll
            for (int p = 0; p < 4; p++) {
                uint32_t br[4];
                ldsm4(br, baseB + so + p * 2048 + (((2 * ks + qhB) ^ xB) << 4));
                mma_tf32(acc[0][2 * p + 0], a0[0], a0[1], a0[2], a0[3], br[0], br[1]);
                mma_tf32(acc[0][2 * p + 1], a0[0], a0[1], a0[2], a0[3], br[2], br[3]);
                mma_tf32(acc[1][2 * p + 0], a1[0], a1[1], a1[2], a1[3], br[0], br[1]);
                mma_tf32(acc[1][2 * p + 1], a1[0], a1[1], a1[2], a1[3], br[2], br[3]);
            }
        }
    }

    // epilogue
    #pragma unroll
    for (int mi = 0; mi < 2; mi++) {
        int rr = row0 + m0 + 16 * mi + r;
        #pragma unroll
        for (int nj = 0; nj < 8; nj++) {
            int cc = col0 + n0 + 8 * nj + 2 * l;
            float b0 = bias[cc], b1 = bias[cc + 1];
            float v0 = acc[mi][nj][0] + b0;
            float v1 = acc[mi][nj][1] + b1;
            float v2 = acc[mi][nj][2] + b0;
            float v3 = acc[mi][nj][3] + b1;
            if (EPI == 1) {
                const float* rp0 = res + (size_t)rr * N + cc;
                const float* rp1 = res + (size_t)(rr + 8) * N + cc;
                v0 += rp0[0]; v1 += rp0[1];
                v2 += rp1[0]; v3 += rp1[1];
            }
            if (EPI == 2) {
                v0 = 0.5f * v0 * (1.f + erff(v0 * 0.70710678118654752f));
                v1 = 0.5f * v1 * (1.f + erff(v1 * 0.70710678118654752f));
                v2 = 0.5f * v2 * (1.f + erff(v2 * 0.70710678118654752f));
                v3 = 0.5f * v3 * (1.f + erff(v3 * 0.70710678118654752f));
            }
            if (TF32OUT) {
                v0 = tf32r(v0); v1 = tf32r(v1); v2 = tf32r(v2); v3 = tf32r(v3);
            }
            float2 o01 = { v0, v1 };
            float2 o23 = { v2, v3 };
            *(float2*)(C + (size_t)rr * N + cc) = o01;
            *(float2*)(C + (size_t)(rr + 8) * N + cc) = o23;
        }
    }
}

// ================= tensor-core flash attention (tf32 mma) ==================
#define AT_QS   0            // [128][68]
#define AT_KS   8704         // [64][68]   K tile [j][d]
#define AT_VT   13056        // [64][68]   V^T tile [d][j]
#define AT_PS   17408        // [128][68]  probs
#define AT_RELS 26112        // [513]
#define AT_PTS  26625        // [1024]
#define AT_LEX  27649        // [64]
#define AT_MROW 27713        // [128]
#define AT_LROW 27841        // [128]
#define AT_PIDQ 27969        // [128] int
#define AT_PIDK 28097        // [64]  int
#define AT_TOT  28161
#define ATTN_SMEM (AT_TOT * 4)

__global__ __launch_bounds__(256) void attn_mma(
    const float* __restrict__ QKV, const float* __restrict__ rel_emb,
    const float* __restrict__ ptab, const int* __restrict__ pids,
    const float* __restrict__ lex, float* __restrict__ ctx) {
    float* sm = (float*)smem_raw;
    int* smi = (int*)smem_raw;
    const float LOG2E = 1.44269504089f;

    int tid = threadIdx.x;
    int w = tid >> 5, lane = tid & 31;
    int r = lane >> 2, l = lane & 3;
    int h = blockIdx.y, bbx = blockIdx.z;
    int i0 = blockIdx.x * 128;

    for (int i = tid; i < 513; i += 256) sm[AT_RELS + i] = rel_emb[i * HH + h];
    for (int i = tid; i < 1024; i += 256) sm[AT_PTS + i] = ptab[i * HH + h];
    if (tid < 128) {
        smi[AT_PIDQ + tid] = pids[bbx * LL + i0 + tid];
        sm[AT_MROW + tid] = -1e30f;
        sm[AT_LROW + tid] = 0.f;
    }
    {
        int row = tid >> 1, dh = (tid & 1) * 32;
        const float* src = QKV + (size_t)(bbx * LL + i0 + row) * QKVS + h * 64 + dh;
        #pragma unroll
        for (int u = 0; u < 8; u++) {
            float4 v = *(const float4*)(src + u * 4);
            uint4 t = { f2tf32(v.x * 0.125f), f2tf32(v.y * 0.125f),
                        f2tf32(v.z * 0.125f), f2tf32(v.w * 0.125f) };
            *(uint4*)&sm[AT_QS + row * 68 + dh + u * 4] = t;
        }
    }
    __syncthreads();

    uint32_t aq[8][4];
    {
        int m = w * 16 + r;
        #pragma unroll
        for (int kk = 0; kk < 8; kk++) {
            aq[kk][0] = __float_as_uint(sm[AT_QS + m * 68 + kk * 8 + l]);
            aq[kk][1] = __float_as_uint(sm[AT_QS + (m + 8) * 68 + kk * 8 + l]);
            aq[kk][2] = __float_as_uint(sm[AT_QS + m * 68 + kk * 8 + l + 4]);
            aq[kk][3] = __float_as_uint(sm[AT_QS + (m + 8) * 68 + kk * 8 + l + 4]);
        }
    }
    int pq0 = smi[AT_PIDQ + w * 16 + r] * PP;
    int pq1 = smi[AT_PIDQ + w * 16 + r + 8] * PP;

    float o[8][4];
    #pragma unroll
    for (int nj = 0; nj < 8; nj++)
        #pragma unroll
        for (int k = 0; k < 4; k++) o[nj][k] = 0.f;

    for (int t = 0; t < 16; t++) {
        int j0 = t * 64;
        {
            int j = tid >> 2, dseg = tid & 3;
            const float* ksrc = QKV + (size_t)(bbx * LL + j0 + j) * QKVS + 768 + h * 64 + dseg * 16;
            const float* vsrc = ksrc + 768;
            #pragma unroll
            for (int u = 0; u < 4; u++) {
                float4 kv = *(const float4*)(ksrc + u * 4);
                uint4 kt = { f2tf32(kv.x), f2tf32(kv.y), f2tf32(kv.z), f2tf32(kv.w) };
                *(uint4*)&sm[AT_KS + j * 68 + dseg * 16 + u * 4] = kt;
                float4 vv = *(const float4*)(vsrc + u * 4);
                int d = dseg * 16 + u * 4;
                sm[AT_VT + (d + 0) * 68 + j] = tf32r(vv.x);
                sm[AT_VT + (d + 1) * 68 + j] = tf32r(vv.y);
                sm[AT_VT + (d + 2) * 68 + j] = tf32r(vv.z);
                sm[AT_VT + (d + 3) * 68 + j] = tf32r(vv.w);
            }
        }
        if (tid < 64) {
            smi[AT_PIDK + tid] = pids[bbx * LL + j0 + tid];
            sm[AT_LEX + tid] = lex[bbx * LL + j0 + tid];
        }
        __syncthreads();

        float s[8][4];
        #pragma unroll
        for (int nj = 0; nj < 8; nj++)
            #pragma unroll
            for (int k = 0; k < 4; k++) s[nj][k] = 0.f;
        #pragma unroll
        for (int kk = 0; kk < 8; kk++) {
            #pragma unroll
            for (int nj = 0; nj < 8; nj++) {
                uint32_t b0 = __float_as_uint(sm[AT_KS + (nj * 8 + r) * 68 + kk * 8 + l]);
                uint32_t b1 = __float_as_uint(sm[AT_KS + (nj * 8 + r) * 68 + kk * 8 + l + 4]);
                mma_tf32(s[nj], aq[kk][0], aq[kk][1], aq[kk][2], aq[kk][3], b0, b1);
            }
        }

        int rg0 = i0 + w * 16 + r, rg1 = rg0 + 8;
        float mx0 = -1e30f, mx1 = -1e30f;
        #pragma unroll
        for (int nj = 0; nj < 8; nj++) {
            int ca = nj * 8 + 2 * l;
            int jga = j0 + ca;
            int pka = smi[AT_PIDK + ca], pkb = smi[AT_PIDK + ca + 1];
            float lxa = sm[AT_LEX + ca], lxb = sm[AT_LEX + ca + 1];
            int ra0 = min(max(jga - rg0, -MAXD_), MAXD_) + MAXD_;
            int rb0 = min(max(jga + 1 - rg0, -MAXD_), MAXD_) + MAXD_;
            int ra1 = min(max(jga - rg1, -MAXD_), MAXD_) + MAXD_;
            int rb1 = min(max(jga + 1 - rg1, -MAXD_), MAXD_) + MAXD_;
            s[nj][0] += sm[AT_RELS + ra0] + sm[AT_PTS + pq0 + pka] + lxa;
            s[nj][1] += sm[AT_RELS + rb0] + sm[AT_PTS + pq0 + pkb] + lxb;
            s[nj][2] += sm[AT_RELS + ra1] + sm[AT_PTS + pq1 + pka] + lxa;
            s[nj][3] += sm[AT_RELS + rb1] + sm[AT_PTS + pq1 + pkb] + lxb;
            mx0 = fmaxf(mx0, fmaxf(s[nj][0], s[nj][1]));
            mx1 = fmaxf(mx1, fmaxf(s[nj][2], s[nj][3]));
        }
        mx0 = fmaxf(mx0, __shfl_xor_sync(0xffffffffu, mx0, 1));
        mx0 = fmaxf(mx0, __shfl_xor_sync(0xffffffffu, mx0, 2));
        mx1 = fmaxf(mx1, __shfl_xor_sync(0xffffffffu, mx1, 1));
        mx1 = fmaxf(mx1, __shfl_xor_sync(0xffffffffu, mx1, 2));

        float mo0 = sm[AT_MROW + w * 16 + r], mo1 = sm[AT_MROW + w * 16 + r + 8];
        float mn0 = fmaxf(mo0, mx0), mn1 = fmaxf(mo1, mx1);
        float al0 = exp2f((mo0 - mn0) * LOG2E), al1 = exp2f((mo1 - mn1) * LOG2E);
        float sum0 = 0.f, sum1 = 0.f;
        #pragma unroll
        for (int nj = 0; nj < 8; nj++) {
            float p0 = exp2f((s[nj][0] - mn0) * LOG2E);
            float p1 = exp2f((s[nj][1] - mn0) * LOG2E);
            float p2 = exp2f((s[nj][2] - mn1) * LOG2E);
            float p3 = exp2f((s[nj][3] - mn1) * LOG2E);
            sum0 += p0 + p1; sum1 += p2 + p3;
            float2 q01 = { p0, p1 };
            float2 q23 = { p2, p3 };
            *(float2*)&sm[AT_PS + (w * 16 + r) * 68 + nj * 8 + 2 * l] = q01;
            *(float2*)&sm[AT_PS + (w * 16 + r + 8) * 68 + nj * 8 + 2 * l] = q23;
            o[nj][0] *= al0; o[nj][1] *= al0; o[nj][2] *= al1; o[nj][3] *= al1;
        }
        sum0 += __shfl_xor_sync(0xffffffffu, sum0, 1);
        sum0 += __shfl_xor_sync(0xffffffffu, sum0, 2);
        sum1 += __shfl_xor_sync(0xffffffffu, sum1, 1);
        sum1 += __shfl_xor_sync(0xffffffffu, sum1, 2);
        if (l == 0) {
            sm[AT_MROW + w * 16 + r] = mn0;
            sm[AT_MROW + w * 16 + r + 8] = mn1;
            sm[AT_LROW + w * 16 + r] = sm[AT_LROW + w * 16 + r] * al0 + sum0;
            sm[AT_LROW + w * 16 + r + 8] = sm[AT_LROW + w * 16 + r + 8] * al1 + sum1;
        }
        __syncwarp();

        #pragma unroll
        for (int kk = 0; kk < 8; kk++) {
            uint32_t ap0 = __float_as_uint(sm[AT_PS + (w * 16 + r) * 68 + kk * 8 + l]);
            uint32_t ap1 = __float_as_uint(sm[AT_PS + (w * 16 + r + 8) * 68 + kk * 8 + l]);
            uint32_t ap2 = __float_as_uint(sm[AT_PS + (w * 16 + r) * 68 + kk * 8 + l + 4]);
            uint32_t ap3 = __float_as_uint(sm[AT_PS + (w * 16 + r + 8) * 68 + kk * 8 + l + 4]);
            #pragma unroll
            for (int nj = 0; nj < 8; nj++) {
                uint32_t b0 = __float_as_uint(sm[AT_VT + (nj * 8 + r) * 68 + kk * 8 + l]);
                uint32_t b1 = __float_as_uint(sm[AT_VT + (nj * 8 + r) * 68 + kk * 8 + l + 4]);
                mma_tf32(o[nj], ap0, ap1, ap2, ap3, b0, b1);
            }
        }
        __syncthreads();
    }

    float inv0 = 1.f / sm[AT_LROW + w * 16 + r];
    float inv1 = 1.f / sm[AT_LROW + w * 16 + r + 8];
    int row0g = bbx * LL + i0 + w * 16 + r;
    #pragma unroll
    for (int nj = 0; nj < 8; nj++) {
        float2 v0 = { tf32r(o[nj][0] * inv0), tf32r(o[nj][1] * inv0) };
        float2 v1 = { tf32r(o[nj][2] * inv1), tf32r(o[nj][3] * inv1) };
        *(float2*)(ctx + (size_t)row0g * DD + h * 64 + nj * 8 + 2 * l) = v0;
        *(float2*)(ctx + (size_t)(row0g + 8) * DD + h * 64 + nj * 8 + 2 * l) = v1;
    }
}

// ---------------- launch ----------------
extern "C" void kernel_launch(void* const* d_in, const int* in_sizes, int n_in,
                              void* d_out, int out_size) {
    const float* x      = (const float*)d_in[0];
    const int*   postag = (const int*)  d_in[1];
    const float* lexm   = (const float*)d_in[2];
    const float* ln1g   = (const float*)d_in[3];
    const float* ln1b   = (const float*)d_in[4];
    const float* Wq     = (const float*)d_in[5];
    const float* bq     = (const float*)d_in[6];
    const float* Wk     = (const float*)d_in[7];
    const float* bk     = (const float*)d_in[8];
    const float* Wv     = (const float*)d_in[9];
    const float* bv     = (const float*)d_in[10];
    const float* Wo     = (const float*)d_in[11];
    const float* bo     = (const float*)d_in[12];
    const float* rel    = (const float*)d_in[13];
    const float* ptab   = (const float*)d_in[14];
    const float* ln2g   = (const float*)d_in[15];
    const float* ln2b   = (const float*)d_in[16];
    const float* W1     = (const float*)d_in[17];
    const float* b1     = (const float*)d_in[18];
    const float* W2     = (const float*)d_in[19];
    const float* b2     = (const float*)d_in[20];
    float* out = (float*)d_out;

    float *qin, *QKVb, *ctx, *res1, *h2, *ff;
    float *WqkvT, *bqkv, *WoT, *W1T, *W2T;
    cudaGetSymbolAddress((void**)&qin,   g_qin);
    cudaGetSymbolAddress((void**)&QKVb,  g_QKV);
    cudaGetSymbolAddress((void**)&ctx,   g_ctx);
    cudaGetSymbolAddress((void**)&res1,  g_res1);
    cudaGetSymbolAddress((void**)&h2,    g_h2);
    cudaGetSymbolAddress((void**)&ff,    g_ff);
    cudaGetSymbolAddress((void**)&WqkvT, g_WqkvT);
    cudaGetSymbolAddress((void**)&bqkv,  g_bqkv);
    cudaGetSymbolAddress((void**)&WoT,   g_WoT);
    cudaGetSymbolAddress((void**)&W1T,   g_W1T);
    cudaGetSymbolAddress((void**)&W2T,   g_W2T);

    cudaFuncSetAttribute(attn_mma, cudaFuncAttributeMaxDynamicSharedMemorySize, ATTN_SMEM);
    cudaFuncSetAttribute(mma_gemm<0,0>, cudaFuncAttributeMaxDynamicSharedMemorySize, GSMEM);
    cudaFuncSetAttribute(mma_gemm<1,0>, cudaFuncAttributeMaxDynamicSharedMemorySize, GSMEM);
    cudaFuncSetAttribute(mma_gemm<2,1>, cudaFuncAttributeMaxDynamicSharedMemorySize, GSMEM);

    // 0: all weight transposes (single launch)
    transpose_all<<<6912, dim3(32, 8)>>>(Wq, Wk, Wv, Wo, W1, W2, bq, bk, bv,
                                         WqkvT, bqkv, WoT, W1T, W2T);
    // 1: LN1
    ln_kernel<<<ML, 256>>>(x, ln1g, ln1b, qin, 1e-6f);
    // 2: fused QKV projection
    mma_gemm<0,0><<<dim3(QKVS / 128, ML / 128), 256, GSMEM>>>(qin, WqkvT, bqkv, nullptr, QKVb, DD, QKVS);
    // 3: tensor-core attention
    attn_mma<<<dim3(LL / 128, HH, BB), 256, ATTN_SMEM>>>(QKVb, rel, ptab, postag, lexm, ctx);
    // 4: output projection + residual
    mma_gemm<1,0><<<dim3(DD / 128, ML / 128), 256, GSMEM>>>(ctx, WoT, bo, x, res1, DD, DD);
    // 5: LN2
    ln_kernel<<<ML, 256>>>(res1, ln2g, ln2b, h2, 1e-5f);
    // 6: FFN up + GELU
    mma_gemm<2,1><<<dim3(FF_ / 128, ML / 128), 256, GSMEM>>>(h2, W1T, b1, nullptr, ff, DD, FF_);
    // 7: FFN down + bias + residual -> out
    mma_gemm<1,0><<<dim3(DD / 128, ML / 128), 256, GSMEM>>>(ff, W2T, b2, res1, out, FF_, DD);
}

// round 8
// speedup vs baseline: 5.8927x; 1.6963x over previous
#include <cuda_runtime.h>
#include <cuda_fp16.h>
#include <math.h>
#include <stdint.h>

// Problem constants
#define BB   4
#define LL   1024
#define DD   768
#define HH   12
#define FF_  3072
#define PP   32
#define MAXD_ 256
#define ML   (BB*LL)   // 4096 rows
#define QKVS 2304      // fused QKV row stride

// ---------------- scratch (device globals; no runtime allocation) ----------
__device__ __half g_qin[ML*DD];
__device__ __half g_QKV[ML*QKVS];
__device__ __half g_Vt[(size_t)BB*HH*64*LL];   // [b][h][d][j]
__device__ __half g_ctx[ML*DD];
__device__ float  g_res1[ML*DD];
__device__ __half g_h2[ML*DD];
__device__ __half g_ff[ML*FF_];
// transposed weights [N,K] fp16
__device__ __half g_WqkvT[QKVS*DD];
__device__ float  g_bqkv[QKVS];
__device__ __half g_WoT[DD*DD];
__device__ __half g_W1T[FF_*DD];
__device__ __half g_W2T[DD*FF_];

// single extern shared symbol for all kernels
extern __shared__ char smem_raw[];

// ======================= helpers =====================
__device__ __forceinline__ uint32_t smem_u32(const void* p) {
    uint32_t a;
    asm("{ .reg .u64 t; cvta.to.shared.u64 t, %1; cvt.u32.u64 %0, t; }" : "=r"(a) : "l"(p));
    return a;
}

#define CP_ASYNC16(dst, src) \
    asm volatile("cp.async.ca.shared.global [%0], [%1], 16;" :: "r"(dst), "l"(src) : "memory")
#define CP_COMMIT()  asm volatile("cp.async.commit_group;" ::: "memory")
#define CP_WAIT1()   asm volatile("cp.async.wait_group 1;" ::: "memory")
#define CP_WAIT0()   asm volatile("cp.async.wait_group 0;" ::: "memory")

__device__ __forceinline__ void mma_f16(float c[4], uint32_t a0, uint32_t a1,
                                        uint32_t a2, uint32_t a3,
                                        uint32_t b0, uint32_t b1) {
    asm volatile(
        "mma.sync.aligned.m16n8k16.row.col.f32.f16.f16.f32 "
        "{%0,%1,%2,%3}, {%4,%5,%6,%7}, {%8,%9}, {%0,%1,%2,%3};"
        : "+f"(c[0]), "+f"(c[1]), "+f"(c[2]), "+f"(c[3])
        : "r"(a0), "r"(a1), "r"(a2), "r"(a3), "r"(b0), "r"(b1));
}
__device__ __forceinline__ void ldsm4(uint32_t r[4], uint32_t addr) {
    asm volatile("ldmatrix.sync.aligned.m8n8.x4.shared.b16 {%0,%1,%2,%3}, [%4];"
                 : "=r"(r[0]), "=r"(r[1]), "=r"(r[2]), "=r"(r[3]) : "r"(addr));
}
__device__ __forceinline__ uint32_t h2u(__half2 h) { return *(uint32_t*)&h; }

// ---------------- all weight transposes in ONE launch (fp16 out) -----------
// blocks: [0,1728) Wq/Wk/Wv -> WqkvT, [1728,2304) Wo, [2304,4608) W1, [4608,6912) W2
__global__ void transpose_all(const float* __restrict__ Wq, const float* __restrict__ Wk,
                              const float* __restrict__ Wv, const float* __restrict__ Wo,
                              const float* __restrict__ W1, const float* __restrict__ W2,
                              const float* __restrict__ bq, const float* __restrict__ bk,
                              const float* __restrict__ bv,
                              __half* __restrict__ WqkvT, float* __restrict__ bqkv,
                              __half* __restrict__ WoT, __half* __restrict__ W1T,
                              __half* __restrict__ W2T) {
    __shared__ float t[32][33];
    int idx = blockIdx.x;
    const float* src; __half* dst; int R, C, bx, by; size_t dstoff = 0;
    if (idx < 1728) {
        int z = idx / 576, lo = idx % 576;
        src = (z == 0) ? Wq : (z == 1) ? Wk : Wv;
        dst = WqkvT; R = DD; C = DD; bx = lo % 24; by = lo / 24;
        dstoff = (size_t)z * DD * DD;
    } else if (idx < 2304) {
        int lo = idx - 1728; src = Wo; dst = WoT; R = DD; C = DD; bx = lo % 24; by = lo / 24;
    } else if (idx < 4608) {
        int lo = idx - 2304; src = W1; dst = W1T; R = DD; C = FF_; bx = lo % 96; by = lo / 96;
    } else {
        int lo = idx - 4608; src = W2; dst = W2T; R = FF_; C = DD; bx = lo % 24; by = lo / 24;
    }
    int c0 = bx * 32, r0 = by * 32;
    int x = threadIdx.x, y = threadIdx.y;
    #pragma unroll
    for (int i = 0; i < 32; i += 8)
        t[y + i][x] = src[(size_t)(r0 + y + i) * C + c0 + x];
    __syncthreads();
    #pragma unroll
    for (int i = 0; i < 32; i += 8)
        dst[dstoff + (size_t)(c0 + y + i) * R + r0 + x] = __float2half(t[x][y + i]);
    if (idx == 0) {
        int tid = y * 32 + x;
        for (int i = tid; i < QKVS; i += 256)
            bqkv[i] = (i < 768) ? bq[i] : (i < 1536) ? bk[i - 768] : bv[i - 1536];
    }
}

// ---------------- V^T global transpose: Vt[b][h][d][j] ---------------------
__global__ void vt_transpose(const __half* __restrict__ QKV, __half* __restrict__ Vt) {
    __shared__ __half t[32][33];
    int j0 = blockIdx.x * 32, d0 = blockIdx.y * 32;
    int bh = blockIdx.z;
    int b = bh / HH, h = bh % HH;
    int x = threadIdx.x, y = threadIdx.y;
    #pragma unroll
    for (int i = 0; i < 32; i += 8)
        t[y + i][x] = QKV[(size_t)(b * LL + j0 + y + i) * QKVS + 1536 + h * 64 + d0 + x];
    __syncthreads();
    #pragma unroll
    for (int i = 0; i < 32; i += 8)
        Vt[((size_t)bh * 64 + d0 + y + i) * LL + j0 + x] = t[x][y + i];
}

// ---------------- LayerNorm (fp16 output) ----------------
__global__ void ln_kernel(const float* __restrict__ x, const float* __restrict__ g,
                          const float* __restrict__ b, __half* __restrict__ y, float eps) {
    int row = blockIdx.x;
    const float* xr = x + (size_t)row * DD;
    __shared__ float red[256];
    int tid = threadIdx.x;

    float s = 0.f;
    for (int d = tid; d < DD; d += 256) s += xr[d];
    red[tid] = s; __syncthreads();
    #pragma unroll
    for (int o = 128; o > 0; o >>= 1) { if (tid < o) red[tid] += red[tid + o]; __syncthreads(); }
    float mu = red[0] * (1.f / DD);
    __syncthreads();

    float v = 0.f;
    for (int d = tid; d < DD; d += 256) { float t = xr[d] - mu; v += t * t; }
    red[tid] = v; __syncthreads();
    #pragma unroll
    for (int o = 128; o > 0; o >>= 1) { if (tid < o) red[tid] += red[tid + o]; __syncthreads(); }
    float inv = rsqrtf(red[0] * (1.f / DD) + eps);

    __half* yr = y + (size_t)row * DD;
    for (int d = tid; d < DD; d += 256)
        yr[d] = __float2half((xr[d] - mu) * inv * g[d] + b[d]);
}

// ====== fp16 mma GEMM with ldmatrix ========================================
// C[M,N] = A[M,K] @ Bt[N,K]^T + epi.  128x128 CTA tile, 8 warps (32x64),
// 3-stage cp.async, K-chunk 64 halves (128B rows, xor swizzle seg^(row&7)).
// EPI: 0 = bias; 1 = bias + residual; 2 = bias + exact GELU
// HALFOUT: 1 -> C is __half, else float
#define NSTAGE 3
#define GSMEM (NSTAGE * 32768)   // 96KB

template<int EPI, int HALFOUT>
__global__ __launch_bounds__(256, 2) void mma_gemm(
    const __half* __restrict__ A, const __half* __restrict__ Bt,
    const float* __restrict__ bias, const float* __restrict__ res,
    void* __restrict__ Cv, int K, int N) {
    uint32_t smem_base = smem_u32(smem_raw);

    int tid = threadIdx.x;
    int wid = tid >> 5, lane = tid & 31;
    int r = lane >> 2, l = lane & 3;
    int quad = lane >> 3, qr = lane & 7;
    int row0 = blockIdx.y * 128, col0 = blockIdx.x * 128;
    int m0 = (wid & 3) * 32, n0 = (wid >> 2) * 64;

    // loader mapping
    int m_l = tid >> 3, s_l = tid & 7;
    const __half* srcA = A + (size_t)(row0 + m_l) * K + s_l * 8;
    const __half* srcB = Bt + (size_t)(col0 + m_l) * K + s_l * 8;
    uint32_t dA0 = smem_base + m_l * 128 + ((s_l ^ (m_l & 7)) << 4);
    uint32_t dB0 = dA0 + 16384;

    // ldmatrix addresses
    int rowA = m0 + ((quad & 1) << 3) + qr;
    int xA = rowA & 7, qhA = quad >> 1;
    uint32_t baseA = smem_base + rowA * 128;
    int rowB = n0 + ((quad >> 1) << 3) + qr;
    int xB = rowB & 7, qhB = quad & 1;
    uint32_t baseB = smem_base + 16384 + rowB * 128;

    int nc = K >> 6;

    float acc[2][8][4];
    #pragma unroll
    for (int i = 0; i < 2; i++)
        #pragma unroll
        for (int j = 0; j < 8; j++)
            #pragma unroll
            for (int k = 0; k < 4; k++) acc[i][j][k] = 0.f;

    #pragma unroll
    for (int s = 0; s < NSTAGE - 1; s++) {
        uint32_t so = s * 32768;
        #pragma unroll
        for (int u = 0; u < 4; u++) {
            CP_ASYNC16(dA0 + so + u * 4096, srcA + (size_t)(s * 64) + (size_t)u * 32 * K);
            CP_ASYNC16(dB0 + so + u * 4096, srcB + (size_t)(s * 64) + (size_t)u * 32 * K);
        }
        CP_COMMIT();
    }

    for (int c = 0; c < nc; c++) {
        CP_WAIT1();
        __syncthreads();
        int nstg = c + NSTAGE - 1;
        if (nstg < nc) {
            uint32_t so = (nstg % NSTAGE) * 32768;
            #pragma unroll
            for (int u = 0; u < 4; u++) {
                CP_ASYNC16(dA0 + so + u * 4096, srcA + (size_t)(nstg * 64) + (size_t)u * 32 * K);
                CP_ASYNC16(dB0 + so + u * 4096, srcB + (size_t)(nstg * 64) + (size_t)u * 32 * K);
            }
        }
        CP_COMMIT();

        uint32_t so = (c % NSTAGE) * 32768;
        #pragma unroll
        for (int ks = 0; ks < 4; ks++) {
            uint32_t a0[4], a1[4];
            ldsm4(a0, baseA + so + (((2 * ks + qhA) ^ xA) << 4));
            ldsm4(a1, baseA + so + 2048 + (((2 * ks + qhA) ^ xA) << 4));
            #pragma unroll
            for (int p = 0; p < 4; p++) {
                uint32_t br[4];
                ldsm4(br, baseB + so + p * 2048 + (((2 * ks + qhB) ^ xB) << 4));
                mma_f16(acc[0][2 * p + 0], a0[0], a0[1], a0[2], a0[3], br[0], br[1]);
                mma_f16(acc[0][2 * p + 1], a0[0], a0[1], a0[2], a0[3], br[2], br[3]);
                mma_f16(acc[1][2 * p + 0], a1[0], a1[1], a1[2], a1[3], br[0], br[1]);
                mma_f16(acc[1][2 * p + 1], a1[0], a1[1], a1[2], a1[3], br[2], br[3]);
            }
        }
    }

    // epilogue
    #pragma unroll
    for (int mi = 0; mi < 2; mi++) {
        int rr = row0 + m0 + 16 * mi + r;
        #pragma unroll
        for (int nj = 0; nj < 8; nj++) {
            int cc = col0 + n0 + 8 * nj + 2 * l;
            float b0 = bias[cc], b1 = bias[cc + 1];
            float v0 = acc[mi][nj][0] + b0;
            float v1 = acc[mi][nj][1] + b1;
            float v2 = acc[mi][nj][2] + b0;
            float v3 = acc[mi][nj][3] + b1;
            if (EPI == 1) {
                const float* rp0 = res + (size_t)rr * N + cc;
                const float* rp1 = res + (size_t)(rr + 8) * N + cc;
                v0 += rp0[0]; v1 += rp0[1];
                v2 += rp1[0]; v3 += rp1[1];
            }
            if (EPI == 2) {
                v0 = 0.5f * v0 * (1.f + erff(v0 * 0.70710678118654752f));
                v1 = 0.5f * v1 * (1.f + erff(v1 * 0.70710678118654752f));
                v2 = 0.5f * v2 * (1.f + erff(v2 * 0.70710678118654752f));
                v3 = 0.5f * v3 * (1.f + erff(v3 * 0.70710678118654752f));
            }
            if (HALFOUT) {
                __half* Ch = (__half*)Cv;
                *(__half2*)(Ch + (size_t)rr * N + cc) = __floats2half2_rn(v0, v1);
                *(__half2*)(Ch + (size_t)(rr + 8) * N + cc) = __floats2half2_rn(v2, v3);
            } else {
                float* Cf = (float*)Cv;
                float2 o01 = { v0, v1 };
                float2 o23 = { v2, v3 };
                *(float2*)(Cf + (size_t)rr * N + cc) = o01;
                *(float2*)(Cf + (size_t)(rr + 8) * N + cc) = o23;
            }
        }
    }
}

// ================= fp16 tensor-core flash attention ========================
// CTA: 128 q x head x batch. 8 warps; warp = 16 rows x 64 cols.
// smem byte offsets:
#define ATB_QS 0         // [128 rows][64 halves]  (128B rows, swizzled)
#define ATB_KS 16384     // [64 j][64 d halves]
#define ATB_VT 24576     // [64 d][64 j halves]
#define ATB_PS 32768     // [128 m][64 j halves]
#define ATB_TB 49152     // float tables
#define TB_REL  0
#define TB_PT   513
#define TB_LEX  1537
#define TB_MROW 1601
#define TB_LROW 1729
#define TB_PIDQ 1857
#define TB_PIDK 1985
#define ATTN_SMEM 57600

__global__ __launch_bounds__(256, 2) void attn_mma(
    const __half* __restrict__ QKV, const __half* __restrict__ Vt,
    const float* __restrict__ rel_emb, const float* __restrict__ ptab,
    const int* __restrict__ pids, const float* __restrict__ lex,
    __half* __restrict__ ctx) {
    char* sb = smem_raw;
    float* tb = (float*)(sb + ATB_TB);
    int* tbi = (int*)tb;
    uint32_t sbase = smem_u32(sb);
    const float LOG2E = 1.44269504089f;

    int tid = threadIdx.x;
    int w = tid >> 5, lane = tid & 31;
    int r = lane >> 2, l = lane & 3;
    int quad = lane >> 3, qr = lane & 7;
    int h = blockIdx.y, bbx = blockIdx.z;
    int i0 = blockIdx.x * 128;

    for (int i = tid; i < 513; i += 256) tb[TB_REL + i] = rel_emb[i * HH + h];
    for (int i = tid; i < 1024; i += 256) tb[TB_PT + i] = ptab[i * HH + h];
    if (tid < 128) {
        tbi[TB_PIDQ + tid] = pids[bbx * LL + i0 + tid];
        tb[TB_MROW + tid] = -1e30f;
        tb[TB_LROW + tid] = 0.f;
    }
    // Q tile: load fp16, scale by 1/8 (exact), store swizzled
    {
        __half2 sc = __float2half2_rn(0.125f);
        #pragma unroll
        for (int u = 0; u < 4; u++) {
            int idx = u * 256 + tid;
            int row = idx >> 3, seg = idx & 7;
            const __half2* src = (const __half2*)(QKV + (size_t)(bbx * LL + i0 + row) * QKVS + h * 64 + seg * 8);
            __half2 v0 = __hmul2(src[0], sc), v1 = __hmul2(src[1], sc);
            __half2 v2 = __hmul2(src[2], sc), v3 = __hmul2(src[3], sc);
            uint4 pk = { h2u(v0), h2u(v1), h2u(v2), h2u(v3) };
            *(uint4*)(sb + ATB_QS + row * 128 + ((seg ^ (row & 7)) << 4)) = pk;
        }
    }
    __syncthreads();

    // Q A-frags resident: rows w*16.., k-steps over d
    uint32_t aq[4][4];
    {
        int rowA = w * 16 + ((quad & 1) << 3) + qr;
        int xA = rowA & 7, qh = quad >> 1;
        uint32_t baseA = sbase + ATB_QS + rowA * 128;
        #pragma unroll
        for (int ks = 0; ks < 4; ks++)
            ldsm4(aq[ks], baseA + (((2 * ks + qh) ^ xA) << 4));
    }
    int pq0 = tbi[TB_PIDQ + w * 16 + r] * PP;
    int pq1 = tbi[TB_PIDQ + w * 16 + r + 8] * PP;

    float o[8][4];
    #pragma unroll
    for (int nj = 0; nj < 8; nj++)
        #pragma unroll
        for (int k = 0; k < 4; k++) o[nj][k] = 0.f;

    // ldsm bases for K (B-frag rows = j), P (A-frag rows = m), V (B-frag rows = d)
    int rowK = ((quad >> 1) << 3) + qr;       // + p*16
    int xK = rowK & 7, qhK = quad & 1;
    uint32_t baseK = sbase + ATB_KS + rowK * 128;
    int rowP = w * 16 + ((quad & 1) << 3) + qr;
    int xP = rowP & 7, qhP = quad >> 1;
    uint32_t baseP = sbase + ATB_PS + rowP * 128;
    uint32_t baseV = sbase + ATB_VT + rowK * 128;  // same row pattern as K

    for (int t = 0; t < 16; t++) {
        int j0 = t * 64;
        // cp.async K tile + Vt tile
        #pragma unroll
        for (int u = 0; u < 2; u++) {
            int idx = u * 256 + tid;
            int row = idx >> 3, seg = idx & 7;
            uint32_t sw = ((seg ^ (row & 7)) << 4);
            CP_ASYNC16(sbase + ATB_KS + row * 128 + sw,
                       QKV + (size_t)(bbx * LL + j0 + row) * QKVS + 768 + h * 64 + seg * 8);
            CP_ASYNC16(sbase + ATB_VT + row * 128 + sw,
                       Vt + ((size_t)(bbx * HH + h) * 64 + row) * LL + j0 + seg * 8);
        }
        CP_COMMIT();
        if (tid < 64) {
            tbi[TB_PIDK + tid] = pids[bbx * LL + j0 + tid];
            tb[TB_LEX + tid] = lex[bbx * LL + j0 + tid];
        }
        CP_WAIT0();
        __syncthreads();

        // S = Q @ K^T  (contraction over d, 4 k-steps)
        float s[8][4];
        #pragma unroll
        for (int nj = 0; nj < 8; nj++)
            #pragma unroll
            for (int k = 0; k < 4; k++) s[nj][k] = 0.f;
        #pragma unroll
        for (int ks = 0; ks < 4; ks++) {
            #pragma unroll
            for (int p = 0; p < 4; p++) {
                uint32_t br[4];
                ldsm4(br, baseK + p * 2048 + (((2 * ks + qhK) ^ xK) << 4));
                mma_f16(s[2 * p + 0], aq[ks][0], aq[ks][1], aq[ks][2], aq[ks][3], br[0], br[1]);
                mma_f16(s[2 * p + 1], aq[ks][0], aq[ks][1], aq[ks][2], aq[ks][3], br[2], br[3]);
            }
        }

        // biases + row max
        int rg0 = i0 + w * 16 + r, rg1 = rg0 + 8;
        float mx0 = -1e30f, mx1 = -1e30f;
        #pragma unroll
        for (int nj = 0; nj < 8; nj++) {
            int ca = nj * 8 + 2 * l;
            int jga = j0 + ca;
            int pka = tbi[TB_PIDK + ca], pkb = tbi[TB_PIDK + ca + 1];
            float lxa = tb[TB_LEX + ca], lxb = tb[TB_LEX + ca + 1];
            int ra0 = min(max(jga - rg0, -MAXD_), MAXD_) + MAXD_;
            int rb0 = min(max(jga + 1 - rg0, -MAXD_), MAXD_) + MAXD_;
            int ra1 = min(max(jga - rg1, -MAXD_), MAXD_) + MAXD_;
            int rb1 = min(max(jga + 1 - rg1, -MAXD_), MAXD_) + MAXD_;
            s[nj][0] += tb[TB_REL + ra0] + tb[TB_PT + pq0 + pka] + lxa;
            s[nj][1] += tb[TB_REL + rb0] + tb[TB_PT + pq0 + pkb] + lxb;
            s[nj][2] += tb[TB_REL + ra1] + tb[TB_PT + pq1 + pka] + lxa;
            s[nj][3] += tb[TB_REL + rb1] + tb[TB_PT + pq1 + pkb] + lxb;
            mx0 = fmaxf(mx0, fmaxf(s[nj][0], s[nj][1]));
            mx1 = fmaxf(mx1, fmaxf(s[nj][2], s[nj][3]));
        }
        mx0 = fmaxf(mx0, __shfl_xor_sync(0xffffffffu, mx0, 1));
        mx0 = fmaxf(mx0, __shfl_xor_sync(0xffffffffu, mx0, 2));
        mx1 = fmaxf(mx1, __shfl_xor_sync(0xffffffffu, mx1, 1));
        mx1 = fmaxf(mx1, __shfl_xor_sync(0xffffffffu, mx1, 2));

        float mo0 = tb[TB_MROW + w * 16 + r], mo1 = tb[TB_MROW + w * 16 + r + 8];
        float mn0 = fmaxf(mo0, mx0), mn1 = fmaxf(mo1, mx1);
        float al0 = exp2f((mo0 - mn0) * LOG2E), al1 = exp2f((mo1 - mn1) * LOG2E);
        float sum0 = 0.f, sum1 = 0.f;
        int m0r = w * 16 + r;
        #pragma unroll
        for (int nj = 0; nj < 8; nj++) {
            float p0 = exp2f((s[nj][0] - mn0) * LOG2E);
            float p1 = exp2f((s[nj][1] - mn0) * LOG2E);
            float p2 = exp2f((s[nj][2] - mn1) * LOG2E);
            float p3 = exp2f((s[nj][3] - mn1) * LOG2E);
            sum0 += p0 + p1; sum1 += p2 + p3;
            *(__half2*)(sb + ATB_PS + m0r * 128 + ((nj ^ (m0r & 7)) << 4) + 4 * l)
                = __floats2half2_rn(p0, p1);
            *(__half2*)(sb + ATB_PS + (m0r + 8) * 128 + ((nj ^ ((m0r + 8) & 7)) << 4) + 4 * l)
                = __floats2half2_rn(p2, p3);
            o[nj][0] *= al0; o[nj][1] *= al0; o[nj][2] *= al1; o[nj][3] *= al1;
        }
        sum0 += __shfl_xor_sync(0xffffffffu, sum0, 1);
        sum0 += __shfl_xor_sync(0xffffffffu, sum0, 2);
        sum1 += __shfl_xor_sync(0xffffffffu, sum1, 1);
        sum1 += __shfl_xor_sync(0xffffffffu, sum1, 2);
        if (l == 0) {
            tb[TB_MROW + m0r] = mn0;
            tb[TB_MROW + m0r + 8] = mn1;
            tb[TB_LROW + m0r] = tb[TB_LROW + m0r] * al0 + sum0;
            tb[TB_LROW + m0r + 8] = tb[TB_LROW + m0r + 8] * al1 + sum1;
        }
        __syncwarp();

        // O += P @ V  (contraction over j, 4 k-steps; B-frags from Vt rows)
        #pragma unroll
        for (int ks = 0; ks < 4; ks++) {
            uint32_t ap[4];
            ldsm4(ap, baseP + (((2 * ks + qhP) ^ xP) << 4));
            #pragma unroll
            for (int p = 0; p < 4; p++) {
                uint32_t bv[4];
                ldsm4(bv, baseV + p * 2048 + (((2 * ks + qhK) ^ xK) << 4));
                mma_f16(o[2 * p + 0], ap[0], ap[1], ap[2], ap[3], bv[0], bv[1]);
                mma_f16(o[2 * p + 1], ap[0], ap[1], ap[2], ap[3], bv[2], bv[3]);
            }
        }
        __syncthreads();
    }

    // finalize
    float inv0 = 1.f / tb[TB_LROW + w * 16 + r];
    float inv1 = 1.f / tb[TB_LROW + w * 16 + r + 8];
    int row0g = bbx * LL + i0 + w * 16 + r;
    #pragma unroll
    for (int nj = 0; nj < 8; nj++) {
        *(__half2*)(ctx + (size_t)row0g * DD + h * 64 + nj * 8 + 2 * l)
            = __floats2half2_rn(o[nj][0] * inv0, o[nj][1] * inv0);
        *(__half2*)(ctx + (size_t)(row0g + 8) * DD + h * 64 + nj * 8 + 2 * l)
            = __floats2half2_rn(o[nj][2] * inv1, o[nj][3] * inv1);
    }
}

// ---------------- launch ----------------
extern "C" void kernel_launch(void* const* d_in, const int* in_sizes, int n_in,
                              void* d_out, int out_size) {
    const float* x      = (const float*)d_in[0];
    const int*   postag = (const int*)  d_in[1];
    const float* lexm   = (const float*)d_in[2];
    const float* ln1g   = (const float*)d_in[3];
    const float* ln1b   = (const float*)d_in[4];
    const float* Wq     = (const float*)d_in[5];
    const float* bq     = (const float*)d_in[6];
    const float* Wk     = (const float*)d_in[7];
    const float* bk     = (const float*)d_in[8];
    const float* Wv     = (const float*)d_in[9];
    const float* bv     = (const float*)d_in[10];
    const float* Wo     = (const float*)d_in[11];
    const float* bo     = (const float*)d_in[12];
    const float* rel    = (const float*)d_in[13];
    const float* ptab   = (const float*)d_in[14];
    const float* ln2g   = (const float*)d_in[15];
    const float* ln2b   = (const float*)d_in[16];
    const float* W1     = (const float*)d_in[17];
    const float* b1     = (const float*)d_in[18];
    const float* W2     = (const float*)d_in[19];
    const float* b2     = (const float*)d_in[20];
    float* out = (float*)d_out;

    __half *qin, *QKVb, *Vt, *ctx, *h2, *ff;
    __half *WqkvT, *WoT, *W1T, *W2T;
    float *res1, *bqkv;
    cudaGetSymbolAddress((void**)&qin,   g_qin);
    cudaGetSymbolAddress((void**)&QKVb,  g_QKV);
    cudaGetSymbolAddress((void**)&Vt,    g_Vt);
    cudaGetSymbolAddress((void**)&ctx,   g_ctx);
    cudaGetSymbolAddress((void**)&res1,  g_res1);
    cudaGetSymbolAddress((void**)&h2,    g_h2);
    cudaGetSymbolAddress((void**)&ff,    g_ff);
    cudaGetSymbolAddress((void**)&WqkvT, g_WqkvT);
    cudaGetSymbolAddress((void**)&bqkv,  g_bqkv);
    cudaGetSymbolAddress((void**)&WoT,   g_WoT);
    cudaGetSymbolAddress((void**)&W1T,   g_W1T);
    cudaGetSymbolAddress((void**)&W2T,   g_W2T);

    cudaFuncSetAttribute(attn_mma, cudaFuncAttributeMaxDynamicSharedMemorySize, ATTN_SMEM);
    cudaFuncSetAttribute(mma_gemm<0,1>, cudaFuncAttributeMaxDynamicSharedMemorySize, GSMEM);
    cudaFuncSetAttribute(mma_gemm<1,0>, cudaFuncAttributeMaxDynamicSharedMemorySize, GSMEM);
    cudaFuncSetAttribute(mma_gemm<2,1>, cudaFuncAttributeMaxDynamicSharedMemorySize, GSMEM);

    // 0: all weight transposes (fp16)
    transpose_all<<<6912, dim3(32, 8)>>>(Wq, Wk, Wv, Wo, W1, W2, bq, bk, bv,
                                         WqkvT, bqkv, WoT, W1T, W2T);
    // 1: LN1 -> fp16
    ln_kernel<<<ML, 256>>>(x, ln1g, ln1b, qin, 1e-6f);
    // 2: fused QKV projection (fp16 out)
    mma_gemm<0,1><<<dim3(QKVS / 128, ML / 128), 256, GSMEM>>>(qin, WqkvT, bqkv, nullptr, QKVb, DD, QKVS);
    // 3: global V^T
    vt_transpose<<<dim3(LL / 32, 2, BB * HH), dim3(32, 8)>>>(QKVb, Vt);
    // 4: fp16 tensor-core attention
    attn_mma<<<dim3(LL / 128, HH, BB), 256, ATTN_SMEM>>>(QKVb, Vt, rel, ptab, postag, lexm, ctx);
    // 5: output projection + residual (fp32 out)
    mma_gemm<1,0><<<dim3(DD / 128, ML / 128), 256, GSMEM>>>(ctx, WoT, bo, x, res1, DD, DD);
    // 6: LN2 -> fp16
    ln_kernel<<<ML, 256>>>(res1, ln2g, ln2b, h2, 1e-5f);
    // 7: FFN up + GELU (fp16 out)
    mma_gemm<2,1><<<dim3(FF_ / 128, ML / 128), 256, GSMEM>>>(h2, W1T, b1, nullptr, ff, DD, FF_);
    // 8: FFN down + bias + residual -> out (fp32)
    mma_gemm<1,0><<<dim3(DD / 128, ML / 128), 256, GSMEM>>>(ff, W2T, b2, res1, out, FF_, DD);
}